// round 14
// baseline (speedup 1.0000x reference)
#include <cuda_runtime.h>
#include <cuda_bf16.h>
#include <math.h>

#define BB   128
#define TT   25
#define VV   10000
#define EE   512
#define NFE  2048
#define HH   512
#define MAPS 512
#define IN0  1024   // EE + MAPS
#define NBLK 128    // 4 row-groups x 32 col-tiles

#define NPAD 10240  // VV padded to 128
#define KEFF 1536   // 3 x 512 (split-K concat) for logits
#define KCM  48     // logits K chunks of 32

#define KEFF2 3072  // 3 x 1024 for precompute
#define KCM2  96    // precompute K chunks of 32

// ---------------- scratch ----------------
__device__ float g_p[BB * MAPS];
__device__ float g_X0[TT * BB * 1536];
__device__ float g_h0[2][BB * HH];
__device__ float g_h1[2][BB * HH];
__device__ float g_ur0[BB * 1024];
__device__ float g_ur1[BB * 1024];
__device__ float g_bur1[1024];
__device__ float g_bx0[1536];                     // packed [bu0|br0|bc0]

// bf16 split recurrent weights, n-major [n][K]
__device__ __nv_bfloat16 g_W0h[1024 * 512],  g_W0l[1024 * 512];   // [Wu0_h|Wr0_h]
__device__ __nv_bfloat16 g_W1h[512 * 512],   g_W1l[512 * 512];    // Wc0 h-part
__device__ __nv_bfloat16 g_W2h[1024 * 1024], g_W2l[1024 * 1024];  // [Wu1|Wr1]
__device__ __nv_bfloat16 g_W3h[512 * 1024],  g_W3l[512 * 1024];   // Wc1

// bf16 split operands for HMMA logits (row-major, k contiguous)
__device__ __nv_bfloat16 g_A2[TT * BB * KEFF];    // [Ah | Ah | Al] (written by PH3 epilogue)
__device__ __nv_bfloat16 g_B2[NPAD * KEFF];       // [Bh | Bl | Bh], n-major

// bf16 split operands for HMMA precompute
__device__ __nv_bfloat16 g_A2x[TT * BB * KEFF2];  // gathered [emb|p]: [Ah|Ah|Al]
__device__ __nv_bfloat16 g_B2x[1536 * KEFF2];     // x-part weights: [Bh|Bl|Bh], n-major

// group-local store/load barriers (4 groups x 32 blocks)
__device__ volatile int g_gflags[4][32];
__device__ volatile int g_gepoch[4];

__device__ __forceinline__ float sigmoidf(float x) { return 1.f / (1.f + expf(-x)); }
__device__ __forceinline__ float4 ldcg4(const float* p) {
    return __ldcg(reinterpret_cast<const float4*>(p));
}
__device__ __forceinline__ unsigned smem_u32(const void* p) {
    unsigned a;
    asm("{ .reg .u64 t; cvta.to.shared.u64 t, %1; cvt.u32.u64 %0, t; }" : "=r"(a) : "l"(p));
    return a;
}
__device__ __forceinline__ void ldmx4(unsigned* r, unsigned addr) {
    asm volatile("ldmatrix.sync.aligned.m8n8.x4.shared.b16 {%0,%1,%2,%3}, [%4];"
                 : "=r"(r[0]), "=r"(r[1]), "=r"(r[2]), "=r"(r[3]) : "r"(addr));
}
__device__ __forceinline__ void ldmx2(unsigned* r, unsigned addr) {
    asm volatile("ldmatrix.sync.aligned.m8n8.x2.shared.b16 {%0,%1}, [%2];"
                 : "=r"(r[0]), "=r"(r[1]) : "r"(addr));
}
__device__ __forceinline__ void mma16816(float* acc, const unsigned* a, const unsigned* b) {
    asm volatile(
        "mma.sync.aligned.m16n8k16.row.col.f32.bf16.bf16.f32 "
        "{%0,%1,%2,%3}, {%4,%5,%6,%7}, {%8,%9}, {%0,%1,%2,%3};"
        : "+f"(acc[0]), "+f"(acc[1]), "+f"(acc[2]), "+f"(acc[3])
        : "r"(a[0]), "r"(a[1]), "r"(a[2]), "r"(a[3]), "r"(b[0]), "r"(b[1]));
}
// split a float4 into bf16 hi(trunc)/lo(rn residual) pairs
__device__ __forceinline__ void split4(float4 v, uint2& hi, uint2& lo) {
    unsigned bx = __float_as_uint(v.x), by = __float_as_uint(v.y);
    unsigned bz = __float_as_uint(v.z), bw = __float_as_uint(v.w);
    hi.x = __byte_perm(bx, by, 0x7632);
    hi.y = __byte_perm(bz, bw, 0x7632);
    float lx = v.x - __uint_as_float(bx & 0xFFFF0000u);
    float ly = v.y - __uint_as_float(by & 0xFFFF0000u);
    float lz = v.z - __uint_as_float(bz & 0xFFFF0000u);
    float lw = v.w - __uint_as_float(bw & 0xFFFF0000u);
    asm("cvt.rn.bf16x2.f32 %0, %1, %2;" : "=r"(lo.x) : "f"(ly), "f"(lx));
    asm("cvt.rn.bf16x2.f32 %0, %1, %2;" : "=r"(lo.y) : "f"(lw), "f"(lz));
}

__device__ __forceinline__ void gbarg(int grp, int ct, int e) {
    __syncthreads();
    if (ct == 0) {
        if (threadIdx.x > 0 && threadIdx.x < 32) {
            while (g_gflags[grp][threadIdx.x] < e) { }
        }
        __syncthreads();
        if (threadIdx.x == 0) {
            __threadfence();
            g_gepoch[grp] = e;
        }
    } else {
        if (threadIdx.x == 0) {
            __threadfence();
            g_gflags[grp][ct] = e;
            while (g_gepoch[grp] < e) { }
            __threadfence();
        }
    }
    __syncthreads();
}

// ---------------- pack ----------------
__global__ void k_pack(const float* __restrict__ bu1, const float* __restrict__ br1,
                       const float* __restrict__ bu0, const float* __restrict__ br0,
                       const float* __restrict__ bc0) {
    int i = blockIdx.x * blockDim.x + threadIdx.x;
    if (i < 128) { g_gflags[i >> 5][i & 31] = 0; if ((i & 31) == 0) g_gepoch[i >> 5] = 0; }
    if (i < 1024) g_bur1[i] = (i < 512) ? bu1[i] : br1[i - 512];
    if (i < 1536) g_bx0[i] = (i < 512) ? bu0[i] : (i < 1024) ? br0[i - 512] : bc0[i - 1024];
}

// ---------------- weight split + transpose for recurrence ----------------
__global__ void __launch_bounds__(256) k_cvtW(
    const float* __restrict__ Wu0, const float* __restrict__ Wr0,
    const float* __restrict__ Wc0, const float* __restrict__ Wu1,
    const float* __restrict__ Wr1, const float* __restrict__ Wc1)
{
    __shared__ float f[32][33];
    const int ph = blockIdx.z;
    const int NN = (ph == 0 || ph == 2) ? 1024 : 512;
    const int KK = (ph >= 2) ? 1024 : 512;
    if ((int)blockIdx.x * 32 >= NN || (int)blockIdx.y * 32 >= KK) return;
    const int tid = threadIdx.x, tr = tid >> 5, tc = tid & 31;
    __nv_bfloat16* Wh = (ph == 0) ? g_W0h : (ph == 1) ? g_W1h : (ph == 2) ? g_W2h : g_W3h;
    __nv_bfloat16* Wl = (ph == 0) ? g_W0l : (ph == 1) ? g_W1l : (ph == 2) ? g_W2l : g_W3l;
#pragma unroll
    for (int i = 0; i < 4; i++) {
        int kk = blockIdx.y * 32 + tr + i * 8;
        int n  = blockIdx.x * 32 + tc;
        float v;
        if (ph == 0)      v = (n < 512) ? Wu0[(IN0 + kk) * HH + n] : Wr0[(IN0 + kk) * HH + (n - 512)];
        else if (ph == 1) v = Wc0[kk * HH + n];
        else if (ph == 2) v = (n < 512) ? Wu1[kk * HH + n] : Wr1[kk * HH + (n - 512)];
        else              v = Wc1[kk * HH + n];
        f[tr + i * 8][tc] = v;
    }
    __syncthreads();
#pragma unroll
    for (int i = 0; i < 4; i++) {
        int n  = blockIdx.x * 32 + tr + i * 8;
        int kk = blockIdx.y * 32 + tc;
        float wv = f[tc][tr + i * 8];
        __nv_bfloat16 bh = __float2bfloat16(wv);
        __nv_bfloat16 bl = __float2bfloat16(wv - __bfloat162float(bh));
        Wh[(size_t)n * KK + kk] = bh;
        Wl[(size_t)n * KK + kk] = bl;
    }
}

// ---------------- precompute weight split + transpose (x-parts) ----------------
__global__ void __launch_bounds__(256) k_cvtBx(
    const float* __restrict__ Wu0, const float* __restrict__ Wr0,
    const float* __restrict__ Wc0)
{
    __shared__ float f[32][33];
    const int ntile = blockIdx.x;
    const int ktile = blockIdx.y;
    const int tid = threadIdx.x;
    const int tr = tid >> 5, tc = tid & 31;
#pragma unroll
    for (int i = 0; i < 4; i++) {
        int kk = ktile * 32 + tr + i * 8;
        int n  = ntile * 32 + tc;
        float v;
        if (n < 512)       v = Wu0[kk * HH + n];
        else if (n < 1024) v = Wr0[kk * HH + (n - 512)];
        else               v = Wc0[(512 + kk) * HH + (n - 1024)];
        f[tr + i * 8][tc] = v;
    }
    __syncthreads();
#pragma unroll
    for (int i = 0; i < 4; i++) {
        int n  = ntile * 32 + tr + i * 8;
        int kk = ktile * 32 + tc;
        float wv = f[tc][tr + i * 8];
        __nv_bfloat16 bh = __float2bfloat16(wv);
        __nv_bfloat16 bl = __float2bfloat16(wv - __bfloat162float(bh));
        __nv_bfloat16* dst = g_B2x + (size_t)n * KEFF2;
        dst[kk]         = bh;
        dst[1024 + kk]  = bl;
        dst[2048 + kk]  = bh;
    }
}

// ---------------- precompute A gather + split ----------------
__global__ void __launch_bounds__(256) k_cvtAx(const int* __restrict__ tokens,
                                               const float* __restrict__ emb) {
    const int m = blockIdx.x;
    const int b = m & 127, t = m >> 7;
    const int tok = tokens[b * TT + t];
    const int tid = threadIdx.x;
    __nv_bfloat16* dst = g_A2x + (size_t)m * KEFF2;
#pragma unroll
    for (int i = 0; i < 4; i++) {
        int k = tid + i * 256;
        float a = (k < 512) ? emb[(size_t)tok * EE + k] : g_p[b * MAPS + (k - 512)];
        __nv_bfloat16 ah = __float2bfloat16(a);
        __nv_bfloat16 al = __float2bfloat16(a - __bfloat162float(ah));
        dst[k]         = ah;
        dst[1024 + k]  = ah;
        dst[2048 + k]  = al;
    }
}

// ---------------- input layer GEMM ----------------
template <int K, typename Op>
__global__ void __launch_bounds__(256) small_gemm(Op op) {
    __shared__ float As[32][33];
    __shared__ float Bs[32][33];
    const int tid = threadIdx.x;
    const int r0 = tid >> 4;
    const int c0 = tid & 15;
    const int mBase = blockIdx.y * 32;
    const int nBase = blockIdx.x * 32;

    float a00 = 0.f, a01 = 0.f, a10 = 0.f, a11 = 0.f;

    for (int k0 = 0; k0 < K; k0 += 32) {
#pragma unroll
        for (int i = 0; i < 4; i++) {
            int e = tid + i * 256;
            int r = e >> 5, kk = e & 31;
            As[r][kk] = op.loadA(mBase + r, k0 + kk);
        }
#pragma unroll
        for (int i = 0; i < 4; i++) {
            int e = tid + i * 256;
            int kk = e >> 5, n = e & 31;
            Bs[kk][n] = op.loadB(k0 + kk, nBase + n);
        }
        __syncthreads();
#pragma unroll
        for (int kk = 0; kk < 32; kk++) {
            float x0 = As[r0][kk],      x1 = As[r0 + 16][kk];
            float y0 = Bs[kk][c0],      y1 = Bs[kk][c0 + 16];
            a00 += x0 * y0; a01 += x0 * y1;
            a10 += x1 * y0; a11 += x1 * y1;
        }
        __syncthreads();
    }
    op.store(mBase + r0,      nBase + c0,      a00);
    op.store(mBase + r0,      nBase + c0 + 16, a01);
    op.store(mBase + r0 + 16, nBase + c0,      a10);
    op.store(mBase + r0 + 16, nBase + c0 + 16, a11);
}

struct OpP {
    const float* A; const float* Bw; const float* bias;
    __device__ float loadA(int r, int k) const { return A[r * NFE + k]; }
    __device__ float loadB(int k, int n) const { return Bw[k * MAPS + n]; }
    __device__ void store(int r, int n, float acc) const {
        float v = acc + bias[n];
        g_p[r * MAPS + n] = v > 0.f ? v : 0.01f * v;
    }
};

// ---------------- persistent recurrence via HMMA, K-chunk 128 ----------------
template <int PH, int COLS, int KTOT>
__device__ __forceinline__ void run_phase_mma(
    __nv_bfloat16 (*sAh)[136], __nv_bfloat16 (*sAl)[136],
    __nv_bfloat16 (*sBh)[136], __nv_bfloat16 (*sBl)[136],
    float (*red)[32][4],
    int t, int grp, int ct,
    const float* h0c, float* h0n, const float* h1c, float* h1n,
    const __nv_bfloat16* __restrict__ Wh, const __nv_bfloat16* __restrict__ Wl,
    const float* __restrict__ bc1)
{
    const int tid = threadIdx.x;
    const int w = tid >> 5, lane = tid & 31;
    constexpr int F  = COLS / 4;            // frag slots: 8 or 4
    constexpr int KW = 16 / F;              // k-parities: 2 or 4
    constexpr int CH = KTOT / 128;          // chunks: 4 or 8
    const int slot = w & (F - 1);
    const int par  = w / F;
    const int mf = (COLS == 32) ? (slot >> 2) : (slot >> 1);
    const int nf = (COLS == 32) ? (slot & 3) : (slot & 1);
    const int R0 = grp * 32;
    const int cb = ct * COLS;

    const int arow = tid >> 4;
    const int ak   = (tid & 15) << 3;
    bool bhAct, blAct; int bn, bsg;
    if (COLS == 32) {
        bhAct = true; blAct = true; bn = tid >> 4; bsg = tid & 15;
    } else {
        bhAct = tid < 256; blAct = !bhAct;
        int q = bhAct ? tid : tid - 256; bn = q >> 4; bsg = q & 15;
    }

    float acc[4] = {0.f, 0.f, 0.f, 0.f};

    auto loadA4 = [&](int ka) -> float4 {
        int rr = R0 + arow;
        if (PH == 0) {
            return ldcg4(h0c + rr * HH + ka);
        } else if (PH == 1) {
            float4 u = ldcg4(g_ur0 + rr * 1024 + 512 + ka);
            float4 h = ldcg4(h0c + rr * HH + ka);
            return make_float4(u.x * h.x, u.y * h.y, u.z * h.z, u.w * h.w);
        } else if (PH == 2) {
            return (ka < 512) ? ldcg4(h0n + rr * HH + ka)
                              : ldcg4(h1c + rr * HH + (ka - 512));
        } else {
            if (ka < 512) {
                float4 u = ldcg4(g_ur1 + rr * 1024 + 512 + ka);
                float4 h = ldcg4(h1c + rr * HH + ka);
                return make_float4(u.x * h.x, u.y * h.y, u.z * h.z, u.w * h.w);
            }
            return ldcg4(h0n + rr * HH + (ka - 512));
        }
    };

    float4 va0 = loadA4(ak), va1 = loadA4(ak + 4);
    uint4 vbh, vbl;
    if (bhAct) vbh = *reinterpret_cast<const uint4*>(Wh + (size_t)(cb + bn) * KTOT + bsg * 8);
    if (blAct) vbl = *reinterpret_cast<const uint4*>(Wl + (size_t)(cb + bn) * KTOT + bsg * 8);

    const unsigned baseAh = smem_u32(sAh), baseAl = smem_u32(sAl);
    const unsigned baseBh = smem_u32(sBh), baseBl = smem_u32(sBl);

    for (int c = 0; c < CH; c++) {
        {
            uint2 h0p, l0p, h1p, l1p;
            split4(va0, h0p, l0p);
            split4(va1, h1p, l1p);
            *reinterpret_cast<uint2*>(&sAh[arow][ak])     = h0p;
            *reinterpret_cast<uint2*>(&sAl[arow][ak])     = l0p;
            *reinterpret_cast<uint2*>(&sAh[arow][ak + 4]) = h1p;
            *reinterpret_cast<uint2*>(&sAl[arow][ak + 4]) = l1p;
        }
        if (bhAct) *reinterpret_cast<uint4*>(&sBh[bn][bsg * 8]) = vbh;
        if (blAct) *reinterpret_cast<uint4*>(&sBl[bn][bsg * 8]) = vbl;
        __syncthreads();

        if (c + 1 < CH) {
            va0 = loadA4((c + 1) * 128 + ak);
            va1 = loadA4((c + 1) * 128 + ak + 4);
            if (bhAct) vbh = *reinterpret_cast<const uint4*>(Wh + (size_t)(cb + bn) * KTOT + (c + 1) * 128 + bsg * 8);
            if (blAct) vbl = *reinterpret_cast<const uint4*>(Wl + (size_t)(cb + bn) * KTOT + (c + 1) * 128 + bsg * 8);
        }

#pragma unroll
        for (int si = 0; si < 8 / KW; si++) {
            int s = par + si * KW;
            unsigned ah[4], al[4], bh[2], bl[2];
            unsigned aoff = (mf * 16 + (lane & 15)) * 272 + s * 32 + (lane >> 4) * 16;
            ldmx4(ah, baseAh + aoff);
            ldmx4(al, baseAl + aoff);
            unsigned boff = (nf * 8 + (lane & 7)) * 272 + s * 32 + ((lane >> 3) & 1) * 16;
            ldmx2(bh, baseBh + boff);
            ldmx2(bl, baseBl + boff);
            mma16816(acc, ah, bh);
            mma16816(acc, ah, bl);
            mma16816(acc, al, bh);
        }
        __syncthreads();
    }

    // cross-parity reduction
    if (par > 0) {
        float* d = red[(par - 1) * F + slot][lane];
        d[0] = acc[0]; d[1] = acc[1]; d[2] = acc[2]; d[3] = acc[3];
    }
    __syncthreads();
    if (par == 0) {
#pragma unroll
        for (int p = 1; p < KW; p++) {
            float* s = red[(p - 1) * F + slot][lane];
            acc[0] += s[0]; acc[1] += s[1]; acc[2] += s[2]; acc[3] += s[3];
        }
        const int gID = lane >> 2, tig = lane & 3;
#pragma unroll
        for (int half = 0; half < 2; half++) {
            int R   = R0 + mf * 16 + gID + half * 8;
            int cgl = cb + nf * 8 + tig * 2;
            float v0 = acc[half * 2], v1 = acc[half * 2 + 1];
            if (PH == 0) {
                const float* x = g_X0 + (t * BB + R) * 1536 + cgl;
                float2 o = make_float2(sigmoidf(v0 + x[0]), sigmoidf(v1 + x[1]));
                *reinterpret_cast<float2*>(g_ur0 + R * 1024 + cgl) = o;
            } else if (PH == 1) {
                const float* x = g_X0 + (t * BB + R) * 1536 + 1024 + cgl;
                float u0 = __ldcg(g_ur0 + R * 1024 + cgl);
                float u1 = __ldcg(g_ur0 + R * 1024 + cgl + 1);
                float p0 = __ldcg(h0c + R * HH + cgl);
                float p1 = __ldcg(h0c + R * HH + cgl + 1);
                float2 o = make_float2(u0 * p0 + (1.f - u0) * tanhf(v0 + x[0]),
                                       u1 * p1 + (1.f - u1) * tanhf(v1 + x[1]));
                *reinterpret_cast<float2*>(h0n + R * HH + cgl) = o;
            } else if (PH == 2) {
                float2 o = make_float2(sigmoidf(v0 + g_bur1[cgl]),
                                       sigmoidf(v1 + g_bur1[cgl + 1]));
                *reinterpret_cast<float2*>(g_ur1 + R * 1024 + cgl) = o;
            } else {
                float u0 = __ldcg(g_ur1 + R * 1024 + cgl);
                float u1 = __ldcg(g_ur1 + R * 1024 + cgl + 1);
                float p0 = __ldcg(h1c + R * HH + cgl);
                float p1 = __ldcg(h1c + R * HH + cgl + 1);
                float2 o = make_float2(u0 * p0 + (1.f - u0) * tanhf(v0 + bc1[cgl]),
                                       u1 * p1 + (1.f - u1) * tanhf(v1 + bc1[cgl + 1]));
                *reinterpret_cast<float2*>(h1n + R * HH + cgl) = o;
                // fused logits-A split write: A2[m] = [Ah | Ah | Al]
                unsigned b0 = __float_as_uint(o.x), b1 = __float_as_uint(o.y);
                unsigned ahp = __byte_perm(b0, b1, 0x7632);
                float l0 = o.x - __uint_as_float(b0 & 0xFFFF0000u);
                float l1 = o.y - __uint_as_float(b1 & 0xFFFF0000u);
                unsigned alp;
                asm("cvt.rn.bf16x2.f32 %0, %1, %2;" : "=r"(alp) : "f"(l1), "f"(l0));
                __nv_bfloat16* dst = g_A2 + (size_t)(t * BB + R) * KEFF + cgl;
                *reinterpret_cast<unsigned*>(dst)        = ahp;
                *reinterpret_cast<unsigned*>(dst + 512)  = ahp;
                *reinterpret_cast<unsigned*>(dst + 1024) = alp;
            }
        }
    }
}

// Wavefront-paired schedule: layer 1 of step t runs alongside layer 0 of step t+1.
//   PH0(0); bar; PH1(0); bar;
//   for t: { PH2(t); PH0(t+1) } bar; { PH3(t); PH1(t+1) } bar;
// Hazards: pairs read only data behind the previous barrier; outputs disjoint.
__global__ void __launch_bounds__(512, 1) k_recurrence(const float* __restrict__ bc1) {
    __shared__ __align__(16) __nv_bfloat16 sAh[32][136];
    __shared__ __align__(16) __nv_bfloat16 sAl[32][136];
    __shared__ __align__(16) __nv_bfloat16 sBh[32][136];
    __shared__ __align__(16) __nv_bfloat16 sBl[32][136];
    __shared__ float red[12][32][4];
    const int tid = threadIdx.x, blk = blockIdx.x;
    const int grp = blk >> 5, ct = blk & 31;
    int ep = 0;

    {
        int off = grp * 16384 + ct * 512 + tid;
        g_h0[0][off] = 0.f;
        g_h1[0][off] = 0.f;
    }
    gbarg(grp, ct, ++ep);

    // prologue: layer 0 of step 0
    run_phase_mma<0, 32,  512>(sAh, sAl, sBh, sBl, red, 0, grp, ct,
                               g_h0[0], g_h0[1], g_h1[0], g_h1[1], g_W0h, g_W0l, bc1);
    gbarg(grp, ct, ++ep);
    run_phase_mma<1, 16,  512>(sAh, sAl, sBh, sBl, red, 0, grp, ct,
                               g_h0[0], g_h0[1], g_h1[0], g_h1[1], g_W1h, g_W1l, bc1);
    gbarg(grp, ct, ++ep);

    for (int t = 0; t < TT; t++) {
        const int cur  = t & 1;
        const float* h0c  = g_h0[cur];
        float*       h0n  = g_h0[cur ^ 1];
        const float* h1c  = g_h1[cur];
        float*       h1n  = g_h1[cur ^ 1];
        const int cur2 = (t + 1) & 1;
        const float* h0c2 = g_h0[cur2];
        float*       h0n2 = g_h0[cur2 ^ 1];
        const float* h1c2 = g_h1[cur2];
        float*       h1n2 = g_h1[cur2 ^ 1];

        // pair A: layer-1 gates of t + layer-0 gates of t+1 (both read h0n(t))
        run_phase_mma<2, 32, 1024>(sAh, sAl, sBh, sBl, red, t, grp, ct,
                                   h0c, h0n, h1c, h1n, g_W2h, g_W2l, bc1);
        if (t + 1 < TT)
            run_phase_mma<0, 32,  512>(sAh, sAl, sBh, sBl, red, t + 1, grp, ct,
                                       h0c2, h0n2, h1c2, h1n2, g_W0h, g_W0l, bc1);
        gbarg(grp, ct, ++ep);

        // pair B: layer-1 candidate of t + layer-0 candidate of t+1
        run_phase_mma<3, 16, 1024>(sAh, sAl, sBh, sBl, red, t, grp, ct,
                                   h0c, h0n, h1c, h1n, g_W3h, g_W3l, bc1);
        if (t + 1 < TT) {
            run_phase_mma<1, 16,  512>(sAh, sAl, sBh, sBl, red, t + 1, grp, ct,
                                       h0c2, h0n2, h1c2, h1n2, g_W1h, g_W1l, bc1);
            gbarg(grp, ct, ++ep);
        }
        // final iteration: no trailing barrier (stream order covers later kernels)
    }
}

// ---------------- bf16 split prep for logits B ----------------
__global__ void __launch_bounds__(256) k_cvtB(const float* __restrict__ Wout) {
    __shared__ float f[32][33];
    const int ntile = blockIdx.x;
    const int ktile = blockIdx.y;
    const int tid = threadIdx.x;
    const int tr = tid >> 5, tc = tid & 31;
#pragma unroll
    for (int i = 0; i < 4; i++) {
        int kk = ktile * 32 + tr + i * 8;
        int n = ntile * 32 + tc;
        f[tr + i * 8][tc] = (n < VV) ? Wout[kk * VV + n] : 0.f;
    }
    __syncthreads();
#pragma unroll
    for (int i = 0; i < 4; i++) {
        int n = ntile * 32 + tr + i * 8;
        int kk = ktile * 32 + tc;
        float w = f[tc][tr + i * 8];
        __nv_bfloat16 bh = __float2bfloat16(w);
        __nv_bfloat16 bl = __float2bfloat16(w - __bfloat162float(bh));
        __nv_bfloat16* dst = g_B2 + (size_t)n * KEFF;
        dst[kk]        = bh;
        dst[512 + kk]  = bl;
        dst[1024 + kk] = bh;
    }
}

// ---------------- generic HMMA GEMM core (CTA 128x128, double-buffered) ----------------
template <int KEFFT, int KCMT, bool LOGITS>
__device__ __forceinline__ void hmma_gemm_body(
    const __nv_bfloat16* __restrict__ gA, const __nv_bfloat16* __restrict__ gB,
    const float* __restrict__ bias, float* __restrict__ out, int nt, int mt,
    __nv_bfloat16 (*sA)[128 * 40], __nv_bfloat16 (*sB)[128 * 40])
{
    const int tid = threadIdx.x;
    const int warp = tid >> 5, lane = tid & 31;
    const int wm = warp >> 2, wn = warp & 3;

    float acc[4][4][4];
#pragma unroll
    for (int a = 0; a < 4; a++)
#pragma unroll
        for (int b = 0; b < 4; b++)
#pragma unroll
            for (int c = 0; c < 4; c++) acc[a][b][c] = 0.f;

    uint4 pa[2], pb[2];
#pragma unroll
    for (int i = 0; i < 2; i++) {
        int s = tid + i * 256, r = s >> 2, sg = s & 3;
        pa[i] = *reinterpret_cast<const uint4*>(gA + (size_t)r * KEFFT + sg * 8);
        pb[i] = *reinterpret_cast<const uint4*>(gB + (size_t)r * KEFFT + sg * 8);
    }

    for (int kc = 0; kc < KCMT; kc++) {
        int buf = kc & 1;
#pragma unroll
        for (int i = 0; i < 2; i++) {
            int s = tid + i * 256, r = s >> 2, sg = s & 3;
            *reinterpret_cast<uint4*>(&sA[buf][r * 40 + sg * 8]) = pa[i];
            *reinterpret_cast<uint4*>(&sB[buf][r * 40 + sg * 8]) = pb[i];
        }
        __syncthreads();

        if (kc + 1 < KCMT) {
            int k0 = (kc + 1) * 32;
#pragma unroll
            for (int i = 0; i < 2; i++) {
                int s = tid + i * 256, r = s >> 2, sg = s & 3;
                pa[i] = *reinterpret_cast<const uint4*>(gA + (size_t)r * KEFFT + k0 + sg * 8);
                pb[i] = *reinterpret_cast<const uint4*>(gB + (size_t)r * KEFFT + k0 + sg * 8);
            }
        }

        unsigned sAb = smem_u32(sA[buf]);
        unsigned sBb = smem_u32(sB[buf]);
#pragma unroll
        for (int kf = 0; kf < 2; kf++) {
            unsigned a[4][4], b[4][2];
#pragma unroll
            for (int mf = 0; mf < 4; mf++) {
                int r = wm * 64 + mf * 16 + (lane & 15);
                ldmx4(a[mf], sAb + r * 80 + kf * 32 + (lane >> 4) * 16);
            }
#pragma unroll
            for (int nf = 0; nf < 4; nf++) {
                int n = wn * 32 + nf * 8 + (lane & 7);
                ldmx2(b[nf], sBb + n * 80 + kf * 32 + ((lane >> 3) & 1) * 16);
            }
#pragma unroll
            for (int mf = 0; mf < 4; mf++)
#pragma unroll
                for (int nf = 0; nf < 4; nf++)
                    mma16816(acc[mf][nf], a[mf], b[nf]);
        }
        __syncthreads();
    }

    const int gID = lane >> 2, tig = lane & 3;
#pragma unroll
    for (int mf = 0; mf < 4; mf++) {
#pragma unroll
        for (int half = 0; half < 2; half++) {
            int gm = mt * 128 + wm * 64 + mf * 16 + gID + half * 8;
            float* orow;
            if (LOGITS) {
                int tt = gm >> 7, bb = gm & 127;
                orow = out + ((size_t)bb * TT + tt) * VV;
            } else {
                orow = out + (size_t)gm * 1536;
            }
#pragma unroll
            for (int nf = 0; nf < 4; nf++) {
                int n = nt * 128 + wn * 32 + nf * 8 + tig * 2;
                float v0 = acc[mf][nf][half * 2 + 0];
                float v1 = acc[mf][nf][half * 2 + 1];
                if (LOGITS) {
                    if (n + 1 < VV) {
                        float2 o = make_float2(v0 + bias[n], v1 + bias[n + 1]);
                        *reinterpret_cast<float2*>(orow + n) = o;
                    } else if (n < VV) {
                        orow[n] = v0 + bias[n];
                    }
                } else {
                    float2 o = make_float2(v0 + bias[n], v1 + bias[n + 1]);
                    *reinterpret_cast<float2*>(orow + n) = o;
                }
            }
        }
    }
}

__global__ void __launch_bounds__(256) k_logits_mma(const float* __restrict__ bout,
                                                    float* __restrict__ out)
{
    __shared__ __align__(16) __nv_bfloat16 sA[2][128 * 40];
    __shared__ __align__(16) __nv_bfloat16 sB[2][128 * 40];
    const int nt = blockIdx.x, mt = blockIdx.y;
    hmma_gemm_body<KEFF, KCM, true>(
        g_A2 + (size_t)(mt * 128) * KEFF, g_B2 + (size_t)(nt * 128) * KEFF,
        bout, out, nt, mt, sA, sB);
}

__global__ void __launch_bounds__(256) k_precompute_mma(float* __restrict__ dummy)
{
    __shared__ __align__(16) __nv_bfloat16 sA[2][128 * 40];
    __shared__ __align__(16) __nv_bfloat16 sB[2][128 * 40];
    const int nt = blockIdx.x, mt = blockIdx.y;
    hmma_gemm_body<KEFF2, KCM2, false>(
        g_A2x + (size_t)(mt * 128) * KEFF2, g_B2x + (size_t)(nt * 128) * KEFF2,
        g_bx0, g_X0, nt, mt, sA, sB);
}

__global__ void k_hidden(float* __restrict__ outh) {
    int i = blockIdx.x * blockDim.x + threadIdx.x;
    if (i < BB * HH) {
        outh[i]           = g_h0[1][i];
        outh[BB * HH + i] = g_h1[1][i];
    }
}

// ---------------- launch ----------------
extern "C" void kernel_launch(void* const* d_in, const int* in_sizes, int n_in,
                              void* d_out, int out_size) {
    const int*   tokens = (const int*)d_in[0];     // int32 (JAX x64 disabled)
    const float* cnn  = (const float*)d_in[1];
    const float* emb  = (const float*)d_in[2];
    const float* Win  = (const float*)d_in[3];
    const float* bin  = (const float*)d_in[4];
    const float* Wout = (const float*)d_in[5];
    const float* bout = (const float*)d_in[6];
    const float* Wu0  = (const float*)d_in[7];
    const float* bu0  = (const float*)d_in[8];
    const float* Wr0  = (const float*)d_in[9];
    const float* br0  = (const float*)d_in[10];
    const float* Wc0  = (const float*)d_in[11];
    const float* bc0  = (const float*)d_in[12];
    const float* Wu1  = (const float*)d_in[13];
    const float* bu1  = (const float*)d_in[14];
    const float* Wr1  = (const float*)d_in[15];
    const float* br1  = (const float*)d_in[16];
    const float* Wc1  = (const float*)d_in[17];
    const float* bc1  = (const float*)d_in[18];
    float* out = (float*)d_out;

    k_pack<<<8, 256>>>(bu1, br1, bu0, br0, bc0);

    // one-time weight splits
    k_cvtW<<<dim3(32, 32, 4), 256>>>(Wu0, Wr0, Wc0, Wu1, Wr1, Wc1);
    k_cvtBx<<<dim3(48, 32), 256>>>(Wu0, Wr0, Wc0);
    k_cvtB<<<dim3(NPAD / 32, 512 / 32), 256>>>(Wout);

    // input layer: p = leaky_relu(cnn @ Win + bin)
    small_gemm<NFE, OpP><<<dim3(MAPS / 32, BB / 32), 256>>>(OpP{cnn, Win, bin});

    // precompute X0 via HMMA
    k_cvtAx<<<TT * BB, 256>>>(tokens, emb);
    k_precompute_mma<<<dim3(1536 / 128, (TT * BB) / 128), 256>>>(nullptr);

    // 25-step recurrence (HMMA persistent, wavefront-paired; writes logits A2 directly)
    k_recurrence<<<NBLK, 512>>>(bc1);

    // HMMA logits
    k_logits_mma<<<dim3(NPAD / 128, (TT * BB) / 128), 256>>>(bout, out);

    k_hidden<<<(BB * HH + 255) / 256, 256>>>(out + (size_t)BB * TT * VV);
}

// round 15
// speedup vs baseline: 1.2570x; 1.2570x over previous
#include <cuda_runtime.h>
#include <cuda_bf16.h>
#include <math.h>

#define BB   128
#define TT   25
#define VV   10000
#define EE   512
#define NFE  2048
#define HH   512
#define MAPS 512
#define IN0  1024   // EE + MAPS
#define NBLK 128    // 4 row-groups x 32 col-tiles

#define NPAD 10240  // VV padded to 128
#define KEFF 1536   // 3 x 512 (split-K concat) for logits
#define KCM  48     // logits K chunks of 32

#define KEFF2 3072  // 3 x 1024 for precompute
#define KCM2  96    // precompute K chunks of 32

// recurrence dynamic smem layout (K-chunk 256)
#define RC_ROWB 264                       // bf16 per staged row (256 + 8 pad)
#define RC_ASZ  (32 * RC_ROWB)            // elems per stage array
#define RC_SMEM (4 * RC_ASZ * 2 + 12 * 32 * 4 * 4)   // 67584 + 6144 = 73728 B

// ---------------- scratch ----------------
__device__ float g_p[BB * MAPS];
__device__ float g_X0[TT * BB * 1536];
__device__ float g_h0[2][BB * HH];
__device__ float g_h1[2][BB * HH];
__device__ float g_ur0[BB * 1024];
__device__ float g_ur1[BB * 1024];
__device__ float g_bur1[1024];
__device__ float g_bx0[1536];                     // packed [bu0|br0|bc0]

// bf16 split recurrent weights, n-major [n][K]
__device__ __nv_bfloat16 g_W0h[1024 * 512],  g_W0l[1024 * 512];   // [Wu0_h|Wr0_h]
__device__ __nv_bfloat16 g_W1h[512 * 512],   g_W1l[512 * 512];    // Wc0 h-part
__device__ __nv_bfloat16 g_W2h[1024 * 1024], g_W2l[1024 * 1024];  // [Wu1|Wr1]
__device__ __nv_bfloat16 g_W3h[512 * 1024],  g_W3l[512 * 1024];   // Wc1

// bf16 split operands for HMMA logits (row-major, k contiguous)
__device__ __nv_bfloat16 g_A2[TT * BB * KEFF];    // [Ah | Ah | Al] (written by PH3 epilogue)
__device__ __nv_bfloat16 g_B2[NPAD * KEFF];       // [Bh | Bl | Bh], n-major

// bf16 split operands for HMMA precompute
__device__ __nv_bfloat16 g_A2x[TT * BB * KEFF2];  // gathered [emb|p]: [Ah|Ah|Al]
__device__ __nv_bfloat16 g_B2x[1536 * KEFF2];     // x-part weights: [Bh|Bl|Bh], n-major

// group-local store/load barriers (4 groups x 32 blocks)
__device__ volatile int g_gflags[4][32];
__device__ volatile int g_gepoch[4];

__device__ __forceinline__ float sigmoidf(float x) { return 1.f / (1.f + expf(-x)); }
__device__ __forceinline__ float4 ldcg4(const float* p) {
    return __ldcg(reinterpret_cast<const float4*>(p));
}
__device__ __forceinline__ unsigned smem_u32(const void* p) {
    unsigned a;
    asm("{ .reg .u64 t; cvta.to.shared.u64 t, %1; cvt.u32.u64 %0, t; }" : "=r"(a) : "l"(p));
    return a;
}
__device__ __forceinline__ void ldmx4(unsigned* r, unsigned addr) {
    asm volatile("ldmatrix.sync.aligned.m8n8.x4.shared.b16 {%0,%1,%2,%3}, [%4];"
                 : "=r"(r[0]), "=r"(r[1]), "=r"(r[2]), "=r"(r[3]) : "r"(addr));
}
__device__ __forceinline__ void ldmx2(unsigned* r, unsigned addr) {
    asm volatile("ldmatrix.sync.aligned.m8n8.x2.shared.b16 {%0,%1}, [%2];"
                 : "=r"(r[0]), "=r"(r[1]) : "r"(addr));
}
__device__ __forceinline__ void mma16816(float* acc, const unsigned* a, const unsigned* b) {
    asm volatile(
        "mma.sync.aligned.m16n8k16.row.col.f32.bf16.bf16.f32 "
        "{%0,%1,%2,%3}, {%4,%5,%6,%7}, {%8,%9}, {%0,%1,%2,%3};"
        : "+f"(acc[0]), "+f"(acc[1]), "+f"(acc[2]), "+f"(acc[3])
        : "r"(a[0]), "r"(a[1]), "r"(a[2]), "r"(a[3]), "r"(b[0]), "r"(b[1]));
}
// split a float4 into bf16 hi(trunc)/lo(rn residual) pairs
__device__ __forceinline__ void split4(float4 v, uint2& hi, uint2& lo) {
    unsigned bx = __float_as_uint(v.x), by = __float_as_uint(v.y);
    unsigned bz = __float_as_uint(v.z), bw = __float_as_uint(v.w);
    hi.x = __byte_perm(bx, by, 0x7632);
    hi.y = __byte_perm(bz, bw, 0x7632);
    float lx = v.x - __uint_as_float(bx & 0xFFFF0000u);
    float ly = v.y - __uint_as_float(by & 0xFFFF0000u);
    float lz = v.z - __uint_as_float(bz & 0xFFFF0000u);
    float lw = v.w - __uint_as_float(bw & 0xFFFF0000u);
    asm("cvt.rn.bf16x2.f32 %0, %1, %2;" : "=r"(lo.x) : "f"(ly), "f"(lx));
    asm("cvt.rn.bf16x2.f32 %0, %1, %2;" : "=r"(lo.y) : "f"(lw), "f"(lz));
}

__device__ __forceinline__ void gbarg(int grp, int ct, int e) {
    __syncthreads();
    if (ct == 0) {
        if (threadIdx.x > 0 && threadIdx.x < 32) {
            while (g_gflags[grp][threadIdx.x] < e) { }
        }
        __syncthreads();
        if (threadIdx.x == 0) {
            __threadfence();
            g_gepoch[grp] = e;
        }
    } else {
        if (threadIdx.x == 0) {
            __threadfence();
            g_gflags[grp][ct] = e;
            while (g_gepoch[grp] < e) { }
            __threadfence();
        }
    }
    __syncthreads();
}

// ---------------- pack ----------------
__global__ void k_pack(const float* __restrict__ bu1, const float* __restrict__ br1,
                       const float* __restrict__ bu0, const float* __restrict__ br0,
                       const float* __restrict__ bc0) {
    int i = blockIdx.x * blockDim.x + threadIdx.x;
    if (i < 128) { g_gflags[i >> 5][i & 31] = 0; if ((i & 31) == 0) g_gepoch[i >> 5] = 0; }
    if (i < 1024) g_bur1[i] = (i < 512) ? bu1[i] : br1[i - 512];
    if (i < 1536) g_bx0[i] = (i < 512) ? bu0[i] : (i < 1024) ? br0[i - 512] : bc0[i - 1024];
}

// ---------------- weight split + transpose for recurrence ----------------
__global__ void __launch_bounds__(256) k_cvtW(
    const float* __restrict__ Wu0, const float* __restrict__ Wr0,
    const float* __restrict__ Wc0, const float* __restrict__ Wu1,
    const float* __restrict__ Wr1, const float* __restrict__ Wc1)
{
    __shared__ float f[32][33];
    const int ph = blockIdx.z;
    const int NN = (ph == 0 || ph == 2) ? 1024 : 512;
    const int KK = (ph >= 2) ? 1024 : 512;
    if ((int)blockIdx.x * 32 >= NN || (int)blockIdx.y * 32 >= KK) return;
    const int tid = threadIdx.x, tr = tid >> 5, tc = tid & 31;
    __nv_bfloat16* Wh = (ph == 0) ? g_W0h : (ph == 1) ? g_W1h : (ph == 2) ? g_W2h : g_W3h;
    __nv_bfloat16* Wl = (ph == 0) ? g_W0l : (ph == 1) ? g_W1l : (ph == 2) ? g_W2l : g_W3l;
#pragma unroll
    for (int i = 0; i < 4; i++) {
        int kk = blockIdx.y * 32 + tr + i * 8;
        int n  = blockIdx.x * 32 + tc;
        float v;
        if (ph == 0)      v = (n < 512) ? Wu0[(IN0 + kk) * HH + n] : Wr0[(IN0 + kk) * HH + (n - 512)];
        else if (ph == 1) v = Wc0[kk * HH + n];
        else if (ph == 2) v = (n < 512) ? Wu1[kk * HH + n] : Wr1[kk * HH + (n - 512)];
        else              v = Wc1[kk * HH + n];
        f[tr + i * 8][tc] = v;
    }
    __syncthreads();
#pragma unroll
    for (int i = 0; i < 4; i++) {
        int n  = blockIdx.x * 32 + tr + i * 8;
        int kk = blockIdx.y * 32 + tc;
        float wv = f[tc][tr + i * 8];
        __nv_bfloat16 bh = __float2bfloat16(wv);
        __nv_bfloat16 bl = __float2bfloat16(wv - __bfloat162float(bh));
        Wh[(size_t)n * KK + kk] = bh;
        Wl[(size_t)n * KK + kk] = bl;
    }
}

// ---------------- precompute weight split + transpose (x-parts) ----------------
__global__ void __launch_bounds__(256) k_cvtBx(
    const float* __restrict__ Wu0, const float* __restrict__ Wr0,
    const float* __restrict__ Wc0)
{
    __shared__ float f[32][33];
    const int ntile = blockIdx.x;
    const int ktile = blockIdx.y;
    const int tid = threadIdx.x;
    const int tr = tid >> 5, tc = tid & 31;
#pragma unroll
    for (int i = 0; i < 4; i++) {
        int kk = ktile * 32 + tr + i * 8;
        int n  = ntile * 32 + tc;
        float v;
        if (n < 512)       v = Wu0[kk * HH + n];
        else if (n < 1024) v = Wr0[kk * HH + (n - 512)];
        else               v = Wc0[(512 + kk) * HH + (n - 1024)];
        f[tr + i * 8][tc] = v;
    }
    __syncthreads();
#pragma unroll
    for (int i = 0; i < 4; i++) {
        int n  = ntile * 32 + tr + i * 8;
        int kk = ktile * 32 + tc;
        float wv = f[tc][tr + i * 8];
        __nv_bfloat16 bh = __float2bfloat16(wv);
        __nv_bfloat16 bl = __float2bfloat16(wv - __bfloat162float(bh));
        __nv_bfloat16* dst = g_B2x + (size_t)n * KEFF2;
        dst[kk]         = bh;
        dst[1024 + kk]  = bl;
        dst[2048 + kk]  = bh;
    }
}

// ---------------- precompute A gather + split ----------------
__global__ void __launch_bounds__(256) k_cvtAx(const int* __restrict__ tokens,
                                               const float* __restrict__ emb) {
    const int m = blockIdx.x;
    const int b = m & 127, t = m >> 7;
    const int tok = tokens[b * TT + t];
    const int tid = threadIdx.x;
    __nv_bfloat16* dst = g_A2x + (size_t)m * KEFF2;
#pragma unroll
    for (int i = 0; i < 4; i++) {
        int k = tid + i * 256;
        float a = (k < 512) ? emb[(size_t)tok * EE + k] : g_p[b * MAPS + (k - 512)];
        __nv_bfloat16 ah = __float2bfloat16(a);
        __nv_bfloat16 al = __float2bfloat16(a - __bfloat162float(ah));
        dst[k]         = ah;
        dst[1024 + k]  = ah;
        dst[2048 + k]  = al;
    }
}

// ---------------- input layer GEMM ----------------
template <int K, typename Op>
__global__ void __launch_bounds__(256) small_gemm(Op op) {
    __shared__ float As[32][33];
    __shared__ float Bs[32][33];
    const int tid = threadIdx.x;
    const int r0 = tid >> 4;
    const int c0 = tid & 15;
    const int mBase = blockIdx.y * 32;
    const int nBase = blockIdx.x * 32;

    float a00 = 0.f, a01 = 0.f, a10 = 0.f, a11 = 0.f;

    for (int k0 = 0; k0 < K; k0 += 32) {
#pragma unroll
        for (int i = 0; i < 4; i++) {
            int e = tid + i * 256;
            int r = e >> 5, kk = e & 31;
            As[r][kk] = op.loadA(mBase + r, k0 + kk);
        }
#pragma unroll
        for (int i = 0; i < 4; i++) {
            int e = tid + i * 256;
            int kk = e >> 5, n = e & 31;
            Bs[kk][n] = op.loadB(k0 + kk, nBase + n);
        }
        __syncthreads();
#pragma unroll
        for (int kk = 0; kk < 32; kk++) {
            float x0 = As[r0][kk],      x1 = As[r0 + 16][kk];
            float y0 = Bs[kk][c0],      y1 = Bs[kk][c0 + 16];
            a00 += x0 * y0; a01 += x0 * y1;
            a10 += x1 * y0; a11 += x1 * y1;
        }
        __syncthreads();
    }
    op.store(mBase + r0,      nBase + c0,      a00);
    op.store(mBase + r0,      nBase + c0 + 16, a01);
    op.store(mBase + r0 + 16, nBase + c0,      a10);
    op.store(mBase + r0 + 16, nBase + c0 + 16, a11);
}

struct OpP {
    const float* A; const float* Bw; const float* bias;
    __device__ float loadA(int r, int k) const { return A[r * NFE + k]; }
    __device__ float loadB(int k, int n) const { return Bw[k * MAPS + n]; }
    __device__ void store(int r, int n, float acc) const {
        float v = acc + bias[n];
        g_p[r * MAPS + n] = v > 0.f ? v : 0.01f * v;
    }
};

// ---------------- persistent recurrence via HMMA, K-chunk 256 ----------------
// Block (grp, ct): rows grp*32..+31, cols ct*COLS..+COLS-1 of phase output.
template <int PH, int COLS, int KTOT>
__device__ __forceinline__ void run_phase_mma(
    __nv_bfloat16 (*sAh)[RC_ROWB], __nv_bfloat16 (*sAl)[RC_ROWB],
    __nv_bfloat16 (*sBh)[RC_ROWB], __nv_bfloat16 (*sBl)[RC_ROWB],
    float (*red)[32][4],
    int t, int grp, int ct,
    const float* h0c, float* h0n, const float* h1c, float* h1n,
    const __nv_bfloat16* __restrict__ Wh, const __nv_bfloat16* __restrict__ Wl,
    const float* __restrict__ bc1)
{
    const int tid = threadIdx.x;
    const int w = tid >> 5, lane = tid & 31;
    constexpr int F  = COLS / 4;            // frag slots: 8 or 4
    constexpr int KW = 16 / F;              // k-parities: 2 or 4
    constexpr int CH = KTOT / 256;          // chunks: 2 or 4
    const int slot = w & (F - 1);
    const int par  = w / F;
    const int mf = (COLS == 32) ? (slot >> 2) : (slot >> 1);
    const int nf = (COLS == 32) ? (slot & 3) : (slot & 1);
    const int R0 = grp * 32;
    const int cb = ct * COLS;

    // A staging: 16 threads/row, each covers 16 floats at ak
    const int arow = tid >> 4;
    const int ak   = (tid & 15) << 4;

    float acc[4] = {0.f, 0.f, 0.f, 0.f};

    auto loadA4 = [&](int ka) -> float4 {
        int rr = R0 + arow;
        if (PH == 0) {
            return ldcg4(h0c + rr * HH + ka);
        } else if (PH == 1) {
            float4 u = ldcg4(g_ur0 + rr * 1024 + 512 + ka);
            float4 h = ldcg4(h0c + rr * HH + ka);
            return make_float4(u.x * h.x, u.y * h.y, u.z * h.z, u.w * h.w);
        } else if (PH == 2) {
            return (ka < 512) ? ldcg4(h0n + rr * HH + ka)
                              : ldcg4(h1c + rr * HH + (ka - 512));
        } else {
            if (ka < 512) {
                float4 u = ldcg4(g_ur1 + rr * 1024 + 512 + ka);
                float4 h = ldcg4(h1c + rr * HH + ka);
                return make_float4(u.x * h.x, u.y * h.y, u.z * h.z, u.w * h.w);
            }
            return ldcg4(h0n + rr * HH + (ka - 512));
        }
    };

    float4 va[4];
#pragma unroll
    for (int i = 0; i < 4; i++) va[i] = loadA4(ak + i * 4);

    // B staging: per half COLS*32 uint4 (COLS rows x 256 bf16)
    uint4 vbh[2], vbl[2];
    if (COLS == 32) {
        // 1024 uint4 per half; all 512 threads do 2 of each
#pragma unroll
        for (int j = 0; j < 2; j++) {
            int idx = tid + j * 512, bn = idx >> 5, bsg = idx & 31;
            vbh[j] = *reinterpret_cast<const uint4*>(Wh + (size_t)(cb + bn) * KTOT + bsg * 8);
            vbl[j] = *reinterpret_cast<const uint4*>(Wl + (size_t)(cb + bn) * KTOT + bsg * 8);
        }
    } else {
        // 512 uint4 per half; threads<256 -> Bh, >=256 -> Bl, 2 each
#pragma unroll
        for (int j = 0; j < 2; j++) {
            if (tid < 256) {
                int idx = tid + j * 256, bn = idx >> 5, bsg = idx & 31;
                vbh[j] = *reinterpret_cast<const uint4*>(Wh + (size_t)(cb + bn) * KTOT + bsg * 8);
            } else {
                int idx = (tid - 256) + j * 256, bn = idx >> 5, bsg = idx & 31;
                vbl[j] = *reinterpret_cast<const uint4*>(Wl + (size_t)(cb + bn) * KTOT + bsg * 8);
            }
        }
    }

    const unsigned baseAh = smem_u32(sAh), baseAl = smem_u32(sAl);
    const unsigned baseBh = smem_u32(sBh), baseBl = smem_u32(sBl);

    for (int c = 0; c < CH; c++) {
        // commit A (split) and B
#pragma unroll
        for (int i = 0; i < 4; i++) {
            uint2 hp, lp;
            split4(va[i], hp, lp);
            *reinterpret_cast<uint2*>(&sAh[arow][ak + i * 4]) = hp;
            *reinterpret_cast<uint2*>(&sAl[arow][ak + i * 4]) = lp;
        }
        if (COLS == 32) {
#pragma unroll
            for (int j = 0; j < 2; j++) {
                int idx = tid + j * 512, bn = idx >> 5, bsg = idx & 31;
                *reinterpret_cast<uint4*>(&sBh[bn][bsg * 8]) = vbh[j];
                *reinterpret_cast<uint4*>(&sBl[bn][bsg * 8]) = vbl[j];
            }
        } else {
#pragma unroll
            for (int j = 0; j < 2; j++) {
                if (tid < 256) {
                    int idx = tid + j * 256, bn = idx >> 5, bsg = idx & 31;
                    *reinterpret_cast<uint4*>(&sBh[bn][bsg * 8]) = vbh[j];
                } else {
                    int idx = (tid - 256) + j * 256, bn = idx >> 5, bsg = idx & 31;
                    *reinterpret_cast<uint4*>(&sBl[bn][bsg * 8]) = vbl[j];
                }
            }
        }
        __syncthreads();

        // prefetch next chunk
        if (c + 1 < CH) {
            int kb = (c + 1) * 256;
#pragma unroll
            for (int i = 0; i < 4; i++) va[i] = loadA4(kb + ak + i * 4);
            if (COLS == 32) {
#pragma unroll
                for (int j = 0; j < 2; j++) {
                    int idx = tid + j * 512, bn = idx >> 5, bsg = idx & 31;
                    vbh[j] = *reinterpret_cast<const uint4*>(Wh + (size_t)(cb + bn) * KTOT + kb + bsg * 8);
                    vbl[j] = *reinterpret_cast<const uint4*>(Wl + (size_t)(cb + bn) * KTOT + kb + bsg * 8);
                }
            } else {
#pragma unroll
                for (int j = 0; j < 2; j++) {
                    if (tid < 256) {
                        int idx = tid + j * 256, bn = idx >> 5, bsg = idx & 31;
                        vbh[j] = *reinterpret_cast<const uint4*>(Wh + (size_t)(cb + bn) * KTOT + kb + bsg * 8);
                    } else {
                        int idx = (tid - 256) + j * 256, bn = idx >> 5, bsg = idx & 31;
                        vbl[j] = *reinterpret_cast<const uint4*>(Wl + (size_t)(cb + bn) * KTOT + kb + bsg * 8);
                    }
                }
            }
        }

#pragma unroll
        for (int si = 0; si < 16 / KW; si++) {
            int s = par + si * KW;
            unsigned ah[4], al[4], bh[2], bl[2];
            unsigned aoff = (mf * 16 + (lane & 15)) * (RC_ROWB * 2) + s * 32 + (lane >> 4) * 16;
            ldmx4(ah, baseAh + aoff);
            ldmx4(al, baseAl + aoff);
            unsigned boff = (nf * 8 + (lane & 7)) * (RC_ROWB * 2) + s * 32 + ((lane >> 3) & 1) * 16;
            ldmx2(bh, baseBh + boff);
            ldmx2(bl, baseBl + boff);
            mma16816(acc, ah, bh);
            mma16816(acc, ah, bl);
            mma16816(acc, al, bh);
        }
        __syncthreads();
    }

    // cross-parity reduction
    if (par > 0) {
        float* d = red[(par - 1) * F + slot][lane];
        d[0] = acc[0]; d[1] = acc[1]; d[2] = acc[2]; d[3] = acc[3];
    }
    __syncthreads();
    if (par == 0) {
#pragma unroll
        for (int p = 1; p < KW; p++) {
            float* s = red[(p - 1) * F + slot][lane];
            acc[0] += s[0]; acc[1] += s[1]; acc[2] += s[2]; acc[3] += s[3];
        }
        const int gID = lane >> 2, tig = lane & 3;
#pragma unroll
        for (int half = 0; half < 2; half++) {
            int R   = R0 + mf * 16 + gID + half * 8;
            int cgl = cb + nf * 8 + tig * 2;
            float v0 = acc[half * 2], v1 = acc[half * 2 + 1];
            if (PH == 0) {
                const float* x = g_X0 + (t * BB + R) * 1536 + cgl;
                float2 o = make_float2(sigmoidf(v0 + x[0]), sigmoidf(v1 + x[1]));
                *reinterpret_cast<float2*>(g_ur0 + R * 1024 + cgl) = o;
            } else if (PH == 1) {
                const float* x = g_X0 + (t * BB + R) * 1536 + 1024 + cgl;
                float u0 = __ldcg(g_ur0 + R * 1024 + cgl);
                float u1 = __ldcg(g_ur0 + R * 1024 + cgl + 1);
                float p0 = __ldcg(h0c + R * HH + cgl);
                float p1 = __ldcg(h0c + R * HH + cgl + 1);
                float2 o = make_float2(u0 * p0 + (1.f - u0) * tanhf(v0 + x[0]),
                                       u1 * p1 + (1.f - u1) * tanhf(v1 + x[1]));
                *reinterpret_cast<float2*>(h0n + R * HH + cgl) = o;
            } else if (PH == 2) {
                float2 o = make_float2(sigmoidf(v0 + g_bur1[cgl]),
                                       sigmoidf(v1 + g_bur1[cgl + 1]));
                *reinterpret_cast<float2*>(g_ur1 + R * 1024 + cgl) = o;
            } else {
                float u0 = __ldcg(g_ur1 + R * 1024 + cgl);
                float u1 = __ldcg(g_ur1 + R * 1024 + cgl + 1);
                float p0 = __ldcg(h1c + R * HH + cgl);
                float p1 = __ldcg(h1c + R * HH + cgl + 1);
                float2 o = make_float2(u0 * p0 + (1.f - u0) * tanhf(v0 + bc1[cgl]),
                                       u1 * p1 + (1.f - u1) * tanhf(v1 + bc1[cgl + 1]));
                *reinterpret_cast<float2*>(h1n + R * HH + cgl) = o;
                // fused logits-A split write: A2[m] = [Ah | Ah | Al]
                unsigned b0 = __float_as_uint(o.x), b1 = __float_as_uint(o.y);
                unsigned ahp = __byte_perm(b0, b1, 0x7632);
                float l0 = o.x - __uint_as_float(b0 & 0xFFFF0000u);
                float l1 = o.y - __uint_as_float(b1 & 0xFFFF0000u);
                unsigned alp;
                asm("cvt.rn.bf16x2.f32 %0, %1, %2;" : "=r"(alp) : "f"(l1), "f"(l0));
                __nv_bfloat16* dst = g_A2 + (size_t)(t * BB + R) * KEFF + cgl;
                *reinterpret_cast<unsigned*>(dst)        = ahp;
                *reinterpret_cast<unsigned*>(dst + 512)  = ahp;
                *reinterpret_cast<unsigned*>(dst + 1024) = alp;
            }
        }
    }
}

// R13 schedule: sequential 4 phases, 3 barriers/step (no barrier after PH3).
__global__ void __launch_bounds__(512, 1) k_recurrence(const float* __restrict__ bc1) {
    extern __shared__ char dsm[];
    __nv_bfloat16 (*sAh)[RC_ROWB] = reinterpret_cast<__nv_bfloat16 (*)[RC_ROWB]>(dsm);
    __nv_bfloat16 (*sAl)[RC_ROWB] = reinterpret_cast<__nv_bfloat16 (*)[RC_ROWB]>(dsm + RC_ASZ * 2);
    __nv_bfloat16 (*sBh)[RC_ROWB] = reinterpret_cast<__nv_bfloat16 (*)[RC_ROWB]>(dsm + RC_ASZ * 4);
    __nv_bfloat16 (*sBl)[RC_ROWB] = reinterpret_cast<__nv_bfloat16 (*)[RC_ROWB]>(dsm + RC_ASZ * 6);
    float (*red)[32][4] = reinterpret_cast<float (*)[32][4]>(dsm + RC_ASZ * 8);

    const int tid = threadIdx.x, blk = blockIdx.x;
    const int grp = blk >> 5, ct = blk & 31;
    int ep = 0;

    {
        int off = grp * 16384 + ct * 512 + tid;
        g_h0[0][off] = 0.f;
        g_h1[0][off] = 0.f;
    }
    gbarg(grp, ct, ++ep);

    for (int t = 0; t < TT; t++) {
        const int cur = t & 1;
        const float* h0c = g_h0[cur];
        float*       h0n = g_h0[cur ^ 1];
        const float* h1c = g_h1[cur];
        float*       h1n = g_h1[cur ^ 1];

        run_phase_mma<0, 32,  512>(sAh, sAl, sBh, sBl, red, t, grp, ct,
                                   h0c, h0n, h1c, h1n, g_W0h, g_W0l, bc1);
        gbarg(grp, ct, ++ep);
        run_phase_mma<1, 16,  512>(sAh, sAl, sBh, sBl, red, t, grp, ct,
                                   h0c, h0n, h1c, h1n, g_W1h, g_W1l, bc1);
        gbarg(grp, ct, ++ep);
        run_phase_mma<2, 32, 1024>(sAh, sAl, sBh, sBl, red, t, grp, ct,
                                   h0c, h0n, h1c, h1n, g_W2h, g_W2l, bc1);
        gbarg(grp, ct, ++ep);
        run_phase_mma<3, 16, 1024>(sAh, sAl, sBh, sBl, red, t, grp, ct,
                                   h0c, h0n, h1c, h1n, g_W3h, g_W3l, bc1);
        if (t != TT - 1) gbarg(grp, ct, ++ep);
        // h1'(t) first read at PH2(t+1), behind 2 later barriers; WARs covered.
    }
}

// ---------------- bf16 split prep for logits B ----------------
__global__ void __launch_bounds__(256) k_cvtB(const float* __restrict__ Wout) {
    __shared__ float f[32][33];
    const int ntile = blockIdx.x;
    const int ktile = blockIdx.y;
    const int tid = threadIdx.x;
    const int tr = tid >> 5, tc = tid & 31;
#pragma unroll
    for (int i = 0; i < 4; i++) {
        int kk = ktile * 32 + tr + i * 8;
        int n = ntile * 32 + tc;
        f[tr + i * 8][tc] = (n < VV) ? Wout[kk * VV + n] : 0.f;
    }
    __syncthreads();
#pragma unroll
    for (int i = 0; i < 4; i++) {
        int n = ntile * 32 + tr + i * 8;
        int kk = ktile * 32 + tc;
        float w = f[tc][tr + i * 8];
        __nv_bfloat16 bh = __float2bfloat16(w);
        __nv_bfloat16 bl = __float2bfloat16(w - __bfloat162float(bh));
        __nv_bfloat16* dst = g_B2 + (size_t)n * KEFF;
        dst[kk]        = bh;
        dst[512 + kk]  = bl;
        dst[1024 + kk] = bh;
    }
}

// ---------------- generic HMMA GEMM core (CTA 128x128, double-buffered) ----------------
template <int KEFFT, int KCMT, bool LOGITS>
__device__ __forceinline__ void hmma_gemm_body(
    const __nv_bfloat16* __restrict__ gA, const __nv_bfloat16* __restrict__ gB,
    const float* __restrict__ bias, float* __restrict__ out, int nt, int mt,
    __nv_bfloat16 (*sA)[128 * 40], __nv_bfloat16 (*sB)[128 * 40])
{
    const int tid = threadIdx.x;
    const int warp = tid >> 5, lane = tid & 31;
    const int wm = warp >> 2, wn = warp & 3;

    float acc[4][4][4];
#pragma unroll
    for (int a = 0; a < 4; a++)
#pragma unroll
        for (int b = 0; b < 4; b++)
#pragma unroll
            for (int c = 0; c < 4; c++) acc[a][b][c] = 0.f;

    uint4 pa[2], pb[2];
#pragma unroll
    for (int i = 0; i < 2; i++) {
        int s = tid + i * 256, r = s >> 2, sg = s & 3;
        pa[i] = *reinterpret_cast<const uint4*>(gA + (size_t)r * KEFFT + sg * 8);
        pb[i] = *reinterpret_cast<const uint4*>(gB + (size_t)r * KEFFT + sg * 8);
    }

    for (int kc = 0; kc < KCMT; kc++) {
        int buf = kc & 1;
#pragma unroll
        for (int i = 0; i < 2; i++) {
            int s = tid + i * 256, r = s >> 2, sg = s & 3;
            *reinterpret_cast<uint4*>(&sA[buf][r * 40 + sg * 8]) = pa[i];
            *reinterpret_cast<uint4*>(&sB[buf][r * 40 + sg * 8]) = pb[i];
        }
        __syncthreads();

        if (kc + 1 < KCMT) {
            int k0 = (kc + 1) * 32;
#pragma unroll
            for (int i = 0; i < 2; i++) {
                int s = tid + i * 256, r = s >> 2, sg = s & 3;
                pa[i] = *reinterpret_cast<const uint4*>(gA + (size_t)r * KEFFT + k0 + sg * 8);
                pb[i] = *reinterpret_cast<const uint4*>(gB + (size_t)r * KEFFT + k0 + sg * 8);
            }
        }

        unsigned sAb = smem_u32(sA[buf]);
        unsigned sBb = smem_u32(sB[buf]);
#pragma unroll
        for (int kf = 0; kf < 2; kf++) {
            unsigned a[4][4], b[4][2];
#pragma unroll
            for (int mf = 0; mf < 4; mf++) {
                int r = wm * 64 + mf * 16 + (lane & 15);
                ldmx4(a[mf], sAb + r * 80 + kf * 32 + (lane >> 4) * 16);
            }
#pragma unroll
            for (int nf = 0; nf < 4; nf++) {
                int n = wn * 32 + nf * 8 + (lane & 7);
                ldmx2(b[nf], sBb + n * 80 + kf * 32 + ((lane >> 3) & 1) * 16);
            }
#pragma unroll
            for (int mf = 0; mf < 4; mf++)
#pragma unroll
                for (int nf = 0; nf < 4; nf++)
                    mma16816(acc[mf][nf], a[mf], b[nf]);
        }
        __syncthreads();
    }

    const int gID = lane >> 2, tig = lane & 3;
#pragma unroll
    for (int mf = 0; mf < 4; mf++) {
#pragma unroll
        for (int half = 0; half < 2; half++) {
            int gm = mt * 128 + wm * 64 + mf * 16 + gID + half * 8;
            float* orow;
            if (LOGITS) {
                int tt = gm >> 7, bb = gm & 127;
                orow = out + ((size_t)bb * TT + tt) * VV;
            } else {
                orow = out + (size_t)gm * 1536;
            }
#pragma unroll
            for (int nf = 0; nf < 4; nf++) {
                int n = nt * 128 + wn * 32 + nf * 8 + tig * 2;
                float v0 = acc[mf][nf][half * 2 + 0];
                float v1 = acc[mf][nf][half * 2 + 1];
                if (LOGITS) {
                    if (n + 1 < VV) {
                        float2 o = make_float2(v0 + bias[n], v1 + bias[n + 1]);
                        *reinterpret_cast<float2*>(orow + n) = o;
                    } else if (n < VV) {
                        orow[n] = v0 + bias[n];
                    }
                } else {
                    float2 o = make_float2(v0 + bias[n], v1 + bias[n + 1]);
                    *reinterpret_cast<float2*>(orow + n) = o;
                }
            }
        }
    }
}

__global__ void __launch_bounds__(256) k_logits_mma(const float* __restrict__ bout,
                                                    float* __restrict__ out)
{
    __shared__ __align__(16) __nv_bfloat16 sA[2][128 * 40];
    __shared__ __align__(16) __nv_bfloat16 sB[2][128 * 40];
    const int nt = blockIdx.x, mt = blockIdx.y;
    hmma_gemm_body<KEFF, KCM, true>(
        g_A2 + (size_t)(mt * 128) * KEFF, g_B2 + (size_t)(nt * 128) * KEFF,
        bout, out, nt, mt, sA, sB);
}

__global__ void __launch_bounds__(256) k_precompute_mma(float* __restrict__ dummy)
{
    __shared__ __align__(16) __nv_bfloat16 sA[2][128 * 40];
    __shared__ __align__(16) __nv_bfloat16 sB[2][128 * 40];
    const int nt = blockIdx.x, mt = blockIdx.y;
    hmma_gemm_body<KEFF2, KCM2, false>(
        g_A2x + (size_t)(mt * 128) * KEFF2, g_B2x + (size_t)(nt * 128) * KEFF2,
        g_bx0, g_X0, nt, mt, sA, sB);
}

__global__ void k_hidden(float* __restrict__ outh) {
    int i = blockIdx.x * blockDim.x + threadIdx.x;
    if (i < BB * HH) {
        outh[i]           = g_h0[1][i];
        outh[BB * HH + i] = g_h1[1][i];
    }
}

// ---------------- launch ----------------
extern "C" void kernel_launch(void* const* d_in, const int* in_sizes, int n_in,
                              void* d_out, int out_size) {
    const int*   tokens = (const int*)d_in[0];     // int32 (JAX x64 disabled)
    const float* cnn  = (const float*)d_in[1];
    const float* emb  = (const float*)d_in[2];
    const float* Win  = (const float*)d_in[3];
    const float* bin  = (const float*)d_in[4];
    const float* Wout = (const float*)d_in[5];
    const float* bout = (const float*)d_in[6];
    const float* Wu0  = (const float*)d_in[7];
    const float* bu0  = (const float*)d_in[8];
    const float* Wr0  = (const float*)d_in[9];
    const float* br0  = (const float*)d_in[10];
    const float* Wc0  = (const float*)d_in[11];
    const float* bc0  = (const float*)d_in[12];
    const float* Wu1  = (const float*)d_in[13];
    const float* bu1  = (const float*)d_in[14];
    const float* Wr1  = (const float*)d_in[15];
    const float* br1  = (const float*)d_in[16];
    const float* Wc1  = (const float*)d_in[17];
    const float* bc1  = (const float*)d_in[18];
    float* out = (float*)d_out;

    cudaFuncSetAttribute(k_recurrence, cudaFuncAttributeMaxDynamicSharedMemorySize, RC_SMEM);

    k_pack<<<8, 256>>>(bu1, br1, bu0, br0, bc0);

    // one-time weight splits
    k_cvtW<<<dim3(32, 32, 4), 256>>>(Wu0, Wr0, Wc0, Wu1, Wr1, Wc1);
    k_cvtBx<<<dim3(48, 32), 256>>>(Wu0, Wr0, Wc0);
    k_cvtB<<<dim3(NPAD / 32, 512 / 32), 256>>>(Wout);

    // input layer: p = leaky_relu(cnn @ Win + bin)
    small_gemm<NFE, OpP><<<dim3(MAPS / 32, BB / 32), 256>>>(OpP{cnn, Win, bin});

    // precompute X0 via HMMA
    k_cvtAx<<<TT * BB, 256>>>(tokens, emb);
    k_precompute_mma<<<dim3(1536 / 128, (TT * BB) / 128), 256>>>(nullptr);

    // 25-step recurrence (HMMA persistent, K-chunk 256; writes logits A2 directly)
    k_recurrence<<<NBLK, 512, RC_SMEM>>>(bc1);

    // HMMA logits
    k_logits_mma<<<dim3(NPAD / 128, (TT * BB) / 128), 256>>>(bout, out);

    k_hidden<<<(BB * HH + 255) / 256, 256>>>(out + (size_t)BB * TT * VV);
}

// round 17
// speedup vs baseline: 1.3521x; 1.0757x over previous
#include <cuda_runtime.h>
#include <cuda_bf16.h>
#include <math.h>

#define BB   128
#define TT   25
#define VV   10000
#define EE   512
#define NFE  2048
#define HH   512
#define MAPS 512
#define IN0  1024   // EE + MAPS
#define NBLK 128    // 4 row-groups x 32 col-tiles

#define NPAD 10240  // VV padded to 128
#define KEFF 1536   // 3 x 512 (split-K concat) for logits
#define KCM  48     // logits K chunks of 32

#define KEFF2 3072  // 3 x 1024 for precompute
#define KCM2  96    // precompute K chunks of 32

// recurrence dynamic smem layout (bytes)
#define RC_A_H    0          // sAh [32][136]
#define RC_A_L    8704       // sAl [32][136]
#define RC_BS_H   17408      // PH2 stage h [32][136]
#define RC_BS_L   26112      // PH2 stage l [32][136]
#define RC_W0H    34816      // persistent W0h slice [32][520]
#define RC_W0L    68096
#define RC_W1H    101376     // [16][520]
#define RC_W1L    118016
#define RC_W3H    134656     // [16][1032]
#define RC_W3L    167680
#define RC_RED    200704     // red [12][32][4] floats
#define RC_SMEM   206848

// ---------------- scratch ----------------
__device__ float g_p[BB * MAPS];
__device__ float g_X0[TT * BB * 1536];
__device__ float g_h0[2][BB * HH];
__device__ float g_h1[2][BB * HH];
__device__ float g_ur0[BB * 1024];
__device__ float g_ur1[BB * 1024];
__device__ float g_bur1[1024];
__device__ float g_bx0[1536];                     // packed [bu0|br0|bc0]

// bf16 split recurrent weights, n-major [n][K]
__device__ __nv_bfloat16 g_W0h[1024 * 512],  g_W0l[1024 * 512];   // [Wu0_h|Wr0_h]
__device__ __nv_bfloat16 g_W1h[512 * 512],   g_W1l[512 * 512];    // Wc0 h-part
__device__ __nv_bfloat16 g_W2h[1024 * 1024], g_W2l[1024 * 1024];  // [Wu1|Wr1]
__device__ __nv_bfloat16 g_W3h[512 * 1024],  g_W3l[512 * 1024];   // Wc1

// bf16 split operands for HMMA logits (row-major, k contiguous)
__device__ __nv_bfloat16 g_A2[TT * BB * KEFF];    // [Ah | Ah | Al] (written by PH3 epilogue)
__device__ __nv_bfloat16 g_B2[NPAD * KEFF];       // [Bh | Bl | Bh], n-major

// bf16 split operands for HMMA precompute
__device__ __nv_bfloat16 g_A2x[TT * BB * KEFF2];  // gathered [emb|p]: [Ah|Ah|Al]
__device__ __nv_bfloat16 g_B2x[1536 * KEFF2];     // x-part weights: [Bh|Bl|Bh], n-major

// group-local store/load barriers (4 groups x 32 blocks)
__device__ volatile int g_gflags[4][32];
__device__ volatile int g_gepoch[4];

__device__ __forceinline__ float sigmoidf(float x) { return 1.f / (1.f + expf(-x)); }
__device__ __forceinline__ float4 ldcg4(const float* p) {
    return __ldcg(reinterpret_cast<const float4*>(p));
}
__device__ __forceinline__ unsigned smem_u32(const void* p) {
    unsigned a;
    asm("{ .reg .u64 t; cvta.to.shared.u64 t, %1; cvt.u32.u64 %0, t; }" : "=r"(a) : "l"(p));
    return a;
}
__device__ __forceinline__ void ldmx4(unsigned* r, unsigned addr) {
    asm volatile("ldmatrix.sync.aligned.m8n8.x4.shared.b16 {%0,%1,%2,%3}, [%4];"
                 : "=r"(r[0]), "=r"(r[1]), "=r"(r[2]), "=r"(r[3]) : "r"(addr));
}
__device__ __forceinline__ void ldmx2(unsigned* r, unsigned addr) {
    asm volatile("ldmatrix.sync.aligned.m8n8.x2.shared.b16 {%0,%1}, [%2];"
                 : "=r"(r[0]), "=r"(r[1]) : "r"(addr));
}
__device__ __forceinline__ void mma16816(float* acc, const unsigned* a, const unsigned* b) {
    asm volatile(
        "mma.sync.aligned.m16n8k16.row.col.f32.bf16.bf16.f32 "
        "{%0,%1,%2,%3}, {%4,%5,%6,%7}, {%8,%9}, {%0,%1,%2,%3};"
        : "+f"(acc[0]), "+f"(acc[1]), "+f"(acc[2]), "+f"(acc[3])
        : "r"(a[0]), "r"(a[1]), "r"(a[2]), "r"(a[3]), "r"(b[0]), "r"(b[1]));
}
// split a float4 into bf16 hi(trunc)/lo(rn residual) pairs
__device__ __forceinline__ void split4(float4 v, uint2& hi, uint2& lo) {
    unsigned bx = __float_as_uint(v.x), by = __float_as_uint(v.y);
    unsigned bz = __float_as_uint(v.z), bw = __float_as_uint(v.w);
    hi.x = __byte_perm(bx, by, 0x7632);
    hi.y = __byte_perm(bz, bw, 0x7632);
    float lx = v.x - __uint_as_float(bx & 0xFFFF0000u);
    float ly = v.y - __uint_as_float(by & 0xFFFF0000u);
    float lz = v.z - __uint_as_float(bz & 0xFFFF0000u);
    float lw = v.w - __uint_as_float(bw & 0xFFFF0000u);
    asm("cvt.rn.bf16x2.f32 %0, %1, %2;" : "=r"(lo.x) : "f"(ly), "f"(lx));
    asm("cvt.rn.bf16x2.f32 %0, %1, %2;" : "=r"(lo.y) : "f"(lw), "f"(lz));
}

__device__ __forceinline__ void gbarg(int grp, int ct, int e) {
    __syncthreads();
    if (ct == 0) {
        if (threadIdx.x > 0 && threadIdx.x < 32) {
            while (g_gflags[grp][threadIdx.x] < e) { }
        }
        __syncthreads();
        if (threadIdx.x == 0) {
            __threadfence();
            g_gepoch[grp] = e;
        }
    } else {
        if (threadIdx.x == 0) {
            __threadfence();
            g_gflags[grp][ct] = e;
            while (g_gepoch[grp] < e) { }
            __threadfence();
        }
    }
    __syncthreads();
}

// ---------------- pack ----------------
__global__ void k_pack(const float* __restrict__ bu1, const float* __restrict__ br1,
                       const float* __restrict__ bu0, const float* __restrict__ br0,
                       const float* __restrict__ bc0) {
    int i = blockIdx.x * blockDim.x + threadIdx.x;
    if (i < 128) { g_gflags[i >> 5][i & 31] = 0; if ((i & 31) == 0) g_gepoch[i >> 5] = 0; }
    if (i < 1024) g_bur1[i] = (i < 512) ? bu1[i] : br1[i - 512];
    if (i < 1536) g_bx0[i] = (i < 512) ? bu0[i] : (i < 1024) ? br0[i - 512] : bc0[i - 1024];
}

// ---------------- weight split + transpose for recurrence ----------------
__global__ void __launch_bounds__(256) k_cvtW(
    const float* __restrict__ Wu0, const float* __restrict__ Wr0,
    const float* __restrict__ Wc0, const float* __restrict__ Wu1,
    const float* __restrict__ Wr1, const float* __restrict__ Wc1)
{
    __shared__ float f[32][33];
    const int ph = blockIdx.z;
    const int NN = (ph == 0 || ph == 2) ? 1024 : 512;
    const int KK = (ph >= 2) ? 1024 : 512;
    if ((int)blockIdx.x * 32 >= NN || (int)blockIdx.y * 32 >= KK) return;
    const int tid = threadIdx.x, tr = tid >> 5, tc = tid & 31;
    __nv_bfloat16* Wh = (ph == 0) ? g_W0h : (ph == 1) ? g_W1h : (ph == 2) ? g_W2h : g_W3h;
    __nv_bfloat16* Wl = (ph == 0) ? g_W0l : (ph == 1) ? g_W1l : (ph == 2) ? g_W2l : g_W3l;
#pragma unroll
    for (int i = 0; i < 4; i++) {
        int kk = blockIdx.y * 32 + tr + i * 8;
        int n  = blockIdx.x * 32 + tc;
        float v;
        if (ph == 0)      v = (n < 512) ? Wu0[(IN0 + kk) * HH + n] : Wr0[(IN0 + kk) * HH + (n - 512)];
        else if (ph == 1) v = Wc0[kk * HH + n];
        else if (ph == 2) v = (n < 512) ? Wu1[kk * HH + n] : Wr1[kk * HH + (n - 512)];
        else              v = Wc1[kk * HH + n];
        f[tr + i * 8][tc] = v;
    }
    __syncthreads();
#pragma unroll
    for (int i = 0; i < 4; i++) {
        int n  = blockIdx.x * 32 + tr + i * 8;
        int kk = blockIdx.y * 32 + tc;
        float wv = f[tc][tr + i * 8];
        __nv_bfloat16 bh = __float2bfloat16(wv);
        __nv_bfloat16 bl = __float2bfloat16(wv - __bfloat162float(bh));
        Wh[(size_t)n * KK + kk] = bh;
        Wl[(size_t)n * KK + kk] = bl;
    }
}

// ---------------- precompute weight split + transpose (x-parts) ----------------
__global__ void __launch_bounds__(256) k_cvtBx(
    const float* __restrict__ Wu0, const float* __restrict__ Wr0,
    const float* __restrict__ Wc0)
{
    __shared__ float f[32][33];
    const int ntile = blockIdx.x;
    const int ktile = blockIdx.y;
    const int tid = threadIdx.x;
    const int tr = tid >> 5, tc = tid & 31;
#pragma unroll
    for (int i = 0; i < 4; i++) {
        int kk = ktile * 32 + tr + i * 8;
        int n  = ntile * 32 + tc;
        float v;
        if (n < 512)       v = Wu0[kk * HH + n];
        else if (n < 1024) v = Wr0[kk * HH + (n - 512)];
        else               v = Wc0[(512 + kk) * HH + (n - 1024)];
        f[tr + i * 8][tc] = v;
    }
    __syncthreads();
#pragma unroll
    for (int i = 0; i < 4; i++) {
        int n  = ntile * 32 + tr + i * 8;
        int kk = ktile * 32 + tc;
        float wv = f[tc][tr + i * 8];
        __nv_bfloat16 bh = __float2bfloat16(wv);
        __nv_bfloat16 bl = __float2bfloat16(wv - __bfloat162float(bh));
        __nv_bfloat16* dst = g_B2x + (size_t)n * KEFF2;
        dst[kk]         = bh;
        dst[1024 + kk]  = bl;
        dst[2048 + kk]  = bh;
    }
}

// ---------------- precompute A gather + split ----------------
__global__ void __launch_bounds__(256) k_cvtAx(const int* __restrict__ tokens,
                                               const float* __restrict__ emb) {
    const int m = blockIdx.x;
    const int b = m & 127, t = m >> 7;
    const int tok = tokens[b * TT + t];
    const int tid = threadIdx.x;
    __nv_bfloat16* dst = g_A2x + (size_t)m * KEFF2;
#pragma unroll
    for (int i = 0; i < 4; i++) {
        int k = tid + i * 256;
        float a = (k < 512) ? emb[(size_t)tok * EE + k] : g_p[b * MAPS + (k - 512)];
        __nv_bfloat16 ah = __float2bfloat16(a);
        __nv_bfloat16 al = __float2bfloat16(a - __bfloat162float(ah));
        dst[k]         = ah;
        dst[1024 + k]  = ah;
        dst[2048 + k]  = al;
    }
}

// ---------------- input layer GEMM ----------------
template <int K, typename Op>
__global__ void __launch_bounds__(256) small_gemm(Op op) {
    __shared__ float As[32][33];
    __shared__ float Bs[32][33];
    const int tid = threadIdx.x;
    const int r0 = tid >> 4;
    const int c0 = tid & 15;
    const int mBase = blockIdx.y * 32;
    const int nBase = blockIdx.x * 32;

    float a00 = 0.f, a01 = 0.f, a10 = 0.f, a11 = 0.f;

    for (int k0 = 0; k0 < K; k0 += 32) {
#pragma unroll
        for (int i = 0; i < 4; i++) {
            int e = tid + i * 256;
            int r = e >> 5, kk = e & 31;
            As[r][kk] = op.loadA(mBase + r, k0 + kk);
        }
#pragma unroll
        for (int i = 0; i < 4; i++) {
            int e = tid + i * 256;
            int kk = e >> 5, n = e & 31;
            Bs[kk][n] = op.loadB(k0 + kk, nBase + n);
        }
        __syncthreads();
#pragma unroll
        for (int kk = 0; kk < 32; kk++) {
            float x0 = As[r0][kk],      x1 = As[r0 + 16][kk];
            float y0 = Bs[kk][c0],      y1 = Bs[kk][c0 + 16];
            a00 += x0 * y0; a01 += x0 * y1;
            a10 += x1 * y0; a11 += x1 * y1;
        }
        __syncthreads();
    }
    op.store(mBase + r0,      nBase + c0,      a00);
    op.store(mBase + r0,      nBase + c0 + 16, a01);
    op.store(mBase + r0 + 16, nBase + c0,      a10);
    op.store(mBase + r0 + 16, nBase + c0 + 16, a11);
}

struct OpP {
    const float* A; const float* Bw; const float* bias;
    __device__ float loadA(int r, int k) const { return A[r * NFE + k]; }
    __device__ float loadB(int k, int n) const { return Bw[k * MAPS + n]; }
    __device__ void store(int r, int n, float acc) const {
        float v = acc + bias[n];
        g_p[r * MAPS + n] = v > 0.f ? v : 0.01f * v;
    }
};

// ---------------- persistent recurrence via HMMA, K-chunk 128 ----------------
// Block (grp, ct): rows grp*32..+31, cols ct*COLS..+COLS-1 of phase output.
// B operand: persistent smem slice for PH0/1/3 (BSTR = row elems), staged for PH2.
template <int PH, int COLS, int KTOT, int BSTR, bool STAGEB>
__device__ __forceinline__ void run_phase_mma(
    __nv_bfloat16 (*sAh)[136], __nv_bfloat16 (*sAl)[136],
    __nv_bfloat16* bH, __nv_bfloat16* bL,
    float (*red)[32][4],
    int t, int grp, int ct,
    const float* h0c, float* h0n, const float* h1c, float* h1n,
    const __nv_bfloat16* __restrict__ Wh, const __nv_bfloat16* __restrict__ Wl,
    const float* __restrict__ bc1)
{
    const int tid = threadIdx.x;
    const int w = tid >> 5, lane = tid & 31;
    constexpr int F  = COLS / 4;            // frag slots: 8 or 4
    constexpr int KW = 16 / F;              // k-parities: 2 or 4
    constexpr int CH = KTOT / 128;          // chunks: 4 or 8
    const int slot = w & (F - 1);
    const int par  = w / F;
    const int mf = (COLS == 32) ? (slot >> 2) : (slot >> 1);
    const int nf = (COLS == 32) ? (slot & 3) : (slot & 1);
    const int R0 = grp * 32;
    const int cb = ct * COLS;

    const int arow = tid >> 4;
    const int ak   = (tid & 15) << 3;
    // B staging roles (STAGEB only; PH2 has COLS==32): 16 threads/row, all threads h+l
    const int bn  = tid >> 4;
    const int bsg = tid & 15;

    float acc[4] = {0.f, 0.f, 0.f, 0.f};

    auto loadA4 = [&](int ka) -> float4 {
        int rr = R0 + arow;
        if (PH == 0) {
            return ldcg4(h0c + rr * HH + ka);
        } else if (PH == 1) {
            float4 u = ldcg4(g_ur0 + rr * 1024 + 512 + ka);
            float4 h = ldcg4(h0c + rr * HH + ka);
            return make_float4(u.x * h.x, u.y * h.y, u.z * h.z, u.w * h.w);
        } else if (PH == 2) {
            return (ka < 512) ? ldcg4(h0n + rr * HH + ka)
                              : ldcg4(h1c + rr * HH + (ka - 512));
        } else {
            if (ka < 512) {
                float4 u = ldcg4(g_ur1 + rr * 1024 + 512 + ka);
                float4 h = ldcg4(h1c + rr * HH + ka);
                return make_float4(u.x * h.x, u.y * h.y, u.z * h.z, u.w * h.w);
            }
            return ldcg4(h0n + rr * HH + (ka - 512));
        }
    };

    float4 va0 = loadA4(ak), va1 = loadA4(ak + 4);
    uint4 vbh, vbl;
    if (STAGEB) {
        vbh = *reinterpret_cast<const uint4*>(Wh + (size_t)(cb + bn) * KTOT + bsg * 8);
        vbl = *reinterpret_cast<const uint4*>(Wl + (size_t)(cb + bn) * KTOT + bsg * 8);
    }

    const unsigned baseAh = smem_u32(sAh), baseAl = smem_u32(sAl);
    const unsigned baseBh = smem_u32(bH), baseBl = smem_u32(bL);

    for (int c = 0; c < CH; c++) {
        {
            uint2 h0p, l0p, h1p, l1p;
            split4(va0, h0p, l0p);
            split4(va1, h1p, l1p);
            *reinterpret_cast<uint2*>(&sAh[arow][ak])     = h0p;
            *reinterpret_cast<uint2*>(&sAl[arow][ak])     = l0p;
            *reinterpret_cast<uint2*>(&sAh[arow][ak + 4]) = h1p;
            *reinterpret_cast<uint2*>(&sAl[arow][ak + 4]) = l1p;
        }
        if (STAGEB) {
            *reinterpret_cast<uint4*>(bH + bn * 136 + bsg * 8) = vbh;
            *reinterpret_cast<uint4*>(bL + bn * 136 + bsg * 8) = vbl;
        }
        __syncthreads();

        if (c + 1 < CH) {
            va0 = loadA4((c + 1) * 128 + ak);
            va1 = loadA4((c + 1) * 128 + ak + 4);
            if (STAGEB) {
                vbh = *reinterpret_cast<const uint4*>(Wh + (size_t)(cb + bn) * KTOT + (c + 1) * 128 + bsg * 8);
                vbl = *reinterpret_cast<const uint4*>(Wl + (size_t)(cb + bn) * KTOT + (c + 1) * 128 + bsg * 8);
            }
        }

#pragma unroll
        for (int si = 0; si < 8 / KW; si++) {
            int s = par + si * KW;
            unsigned ah[4], al[4], bh[2], bl[2];
            unsigned aoff = (mf * 16 + (lane & 15)) * 272 + s * 32 + (lane >> 4) * 16;
            ldmx4(ah, baseAh + aoff);
            ldmx4(al, baseAl + aoff);
            unsigned kByte = (STAGEB ? 0u : (unsigned)(c * 256)) + s * 32;
            unsigned boff = (nf * 8 + (lane & 7)) * (BSTR * 2) + kByte + ((lane >> 3) & 1) * 16;
            ldmx2(bh, baseBh + boff);
            ldmx2(bl, baseBl + boff);
            mma16816(acc, ah, bh);
            mma16816(acc, ah, bl);
            mma16816(acc, al, bh);
        }
        __syncthreads();
    }

    // cross-parity reduction
    if (par > 0) {
        float* d = red[(par - 1) * F + slot][lane];
        d[0] = acc[0]; d[1] = acc[1]; d[2] = acc[2]; d[3] = acc[3];
    }
    __syncthreads();
    if (par == 0) {
#pragma unroll
        for (int p = 1; p < KW; p++) {
            float* s = red[(p - 1) * F + slot][lane];
            acc[0] += s[0]; acc[1] += s[1]; acc[2] += s[2]; acc[3] += s[3];
        }
        const int gID = lane >> 2, tig = lane & 3;
#pragma unroll
        for (int half = 0; half < 2; half++) {
            int R   = R0 + mf * 16 + gID + half * 8;
            int cgl = cb + nf * 8 + tig * 2;
            float v0 = acc[half * 2], v1 = acc[half * 2 + 1];
            if (PH == 0) {
                const float* x = g_X0 + (t * BB + R) * 1536 + cgl;
                float2 o = make_float2(sigmoidf(v0 + x[0]), sigmoidf(v1 + x[1]));
                *reinterpret_cast<float2*>(g_ur0 + R * 1024 + cgl) = o;
            } else if (PH == 1) {
                const float* x = g_X0 + (t * BB + R) * 1536 + 1024 + cgl;
                float u0 = __ldcg(g_ur0 + R * 1024 + cgl);
                float u1 = __ldcg(g_ur0 + R * 1024 + cgl + 1);
                float p0 = __ldcg(h0c + R * HH + cgl);
                float p1 = __ldcg(h0c + R * HH + cgl + 1);
                float2 o = make_float2(u0 * p0 + (1.f - u0) * tanhf(v0 + x[0]),
                                       u1 * p1 + (1.f - u1) * tanhf(v1 + x[1]));
                *reinterpret_cast<float2*>(h0n + R * HH + cgl) = o;
            } else if (PH == 2) {
                float2 o = make_float2(sigmoidf(v0 + g_bur1[cgl]),
                                       sigmoidf(v1 + g_bur1[cgl + 1]));
                *reinterpret_cast<float2*>(g_ur1 + R * 1024 + cgl) = o;
            } else {
                float u0 = __ldcg(g_ur1 + R * 1024 + cgl);
                float u1 = __ldcg(g_ur1 + R * 1024 + cgl + 1);
                float p0 = __ldcg(h1c + R * HH + cgl);
                float p1 = __ldcg(h1c + R * HH + cgl + 1);
                float2 o = make_float2(u0 * p0 + (1.f - u0) * tanhf(v0 + bc1[cgl]),
                                       u1 * p1 + (1.f - u1) * tanhf(v1 + bc1[cgl + 1]));
                *reinterpret_cast<float2*>(h1n + R * HH + cgl) = o;
                // fused logits-A split write: A2[m] = [Ah | Ah | Al]
                unsigned b0 = __float_as_uint(o.x), b1 = __float_as_uint(o.y);
                unsigned ahp = __byte_perm(b0, b1, 0x7632);
                float l0 = o.x - __uint_as_float(b0 & 0xFFFF0000u);
                float l1 = o.y - __uint_as_float(b1 & 0xFFFF0000u);
                unsigned alp;
                asm("cvt.rn.bf16x2.f32 %0, %1, %2;" : "=r"(alp) : "f"(l1), "f"(l0));
                __nv_bfloat16* dst = g_A2 + (size_t)(t * BB + R) * KEFF + cgl;
                *reinterpret_cast<unsigned*>(dst)        = ahp;
                *reinterpret_cast<unsigned*>(dst + 512)  = ahp;
                *reinterpret_cast<unsigned*>(dst + 1024) = alp;
            }
        }
    }
}

// R13 schedule (sequential 4 phases, 3 barriers/step) + persistent weight smem.
__global__ void __launch_bounds__(512, 1) k_recurrence(const float* __restrict__ bc1) {
    extern __shared__ char dsm[];
    __nv_bfloat16 (*sAh)[136] = reinterpret_cast<__nv_bfloat16 (*)[136]>(dsm + RC_A_H);
    __nv_bfloat16 (*sAl)[136] = reinterpret_cast<__nv_bfloat16 (*)[136]>(dsm + RC_A_L);
    __nv_bfloat16* sBsH = reinterpret_cast<__nv_bfloat16*>(dsm + RC_BS_H);
    __nv_bfloat16* sBsL = reinterpret_cast<__nv_bfloat16*>(dsm + RC_BS_L);
    __nv_bfloat16* pW0h = reinterpret_cast<__nv_bfloat16*>(dsm + RC_W0H);
    __nv_bfloat16* pW0l = reinterpret_cast<__nv_bfloat16*>(dsm + RC_W0L);
    __nv_bfloat16* pW1h = reinterpret_cast<__nv_bfloat16*>(dsm + RC_W1H);
    __nv_bfloat16* pW1l = reinterpret_cast<__nv_bfloat16*>(dsm + RC_W1L);
    __nv_bfloat16* pW3h = reinterpret_cast<__nv_bfloat16*>(dsm + RC_W3H);
    __nv_bfloat16* pW3l = reinterpret_cast<__nv_bfloat16*>(dsm + RC_RED - 2 * 33024 + 33024);  // = RC_W3L
    float (*red)[32][4] = reinterpret_cast<float (*)[32][4]>(dsm + RC_RED);

    const int tid = threadIdx.x, blk = blockIdx.x;
    const int grp = blk >> 5, ct = blk & 31;
    int ep = 0;

    // ---- one-time persistent weight slice load ----
    {
        const int cb32 = ct * 32, cb16 = ct * 16;
        // W0: 32 rows x 512 elems (64 uint4/row) = 2048 uint4 per half
        for (int idx = tid; idx < 2048; idx += 512) {
            int r = idx >> 6, sg = idx & 63;
            *reinterpret_cast<uint4*>(pW0h + r * 520 + sg * 8) =
                *reinterpret_cast<const uint4*>(g_W0h + (size_t)(cb32 + r) * 512 + sg * 8);
            *reinterpret_cast<uint4*>(pW0l + r * 520 + sg * 8) =
                *reinterpret_cast<const uint4*>(g_W0l + (size_t)(cb32 + r) * 512 + sg * 8);
        }
        // W1: 16 rows x 512 = 1024 uint4 per half
        for (int idx = tid; idx < 1024; idx += 512) {
            int r = idx >> 6, sg = idx & 63;
            *reinterpret_cast<uint4*>(pW1h + r * 520 + sg * 8) =
                *reinterpret_cast<const uint4*>(g_W1h + (size_t)(cb16 + r) * 512 + sg * 8);
            *reinterpret_cast<uint4*>(pW1l + r * 520 + sg * 8) =
                *reinterpret_cast<const uint4*>(g_W1l + (size_t)(cb16 + r) * 512 + sg * 8);
        }
        // W3: 16 rows x 1024 (128 uint4/row) = 2048 uint4 per half
        for (int idx = tid; idx < 2048; idx += 512) {
            int r = idx >> 7, sg = idx & 127;
            *reinterpret_cast<uint4*>(pW3h + r * 1032 + sg * 8) =
                *reinterpret_cast<const uint4*>(g_W3h + (size_t)(cb16 + r) * 1024 + sg * 8);
            *reinterpret_cast<uint4*>(pW3l + r * 1032 + sg * 8) =
                *reinterpret_cast<const uint4*>(g_W3l + (size_t)(cb16 + r) * 1024 + sg * 8);
        }
        int off = grp * 16384 + ct * 512 + tid;
        g_h0[0][off] = 0.f;
        g_h1[0][off] = 0.f;
    }
    gbarg(grp, ct, ++ep);

    for (int t = 0; t < TT; t++) {
        const int cur = t & 1;
        const float* h0c = g_h0[cur];
        float*       h0n = g_h0[cur ^ 1];
        const float* h1c = g_h1[cur];
        float*       h1n = g_h1[cur ^ 1];

        run_phase_mma<0, 32,  512, 520, false>(sAh, sAl, pW0h, pW0l, red, t, grp, ct,
                                               h0c, h0n, h1c, h1n, nullptr, nullptr, bc1);
        gbarg(grp, ct, ++ep);
        run_phase_mma<1, 16,  512, 520, false>(sAh, sAl, pW1h, pW1l, red, t, grp, ct,
                                               h0c, h0n, h1c, h1n, nullptr, nullptr, bc1);
        gbarg(grp, ct, ++ep);
        run_phase_mma<2, 32, 1024, 136, true >(sAh, sAl, sBsH, sBsL, red, t, grp, ct,
                                               h0c, h0n, h1c, h1n, g_W2h, g_W2l, bc1);
        gbarg(grp, ct, ++ep);
        run_phase_mma<3, 16, 1024, 1032, false>(sAh, sAl, pW3h, pW3l, red, t, grp, ct,
                                                h0c, h0n, h1c, h1n, nullptr, nullptr, bc1);
        if (t != TT - 1) gbarg(grp, ct, ++ep);
        // h1'(t) first read at PH2(t+1), behind 2 later barriers; WARs covered.
    }
}

// ---------------- bf16 split prep for logits B ----------------
__global__ void __launch_bounds__(256) k_cvtB(const float* __restrict__ Wout) {
    __shared__ float f[32][33];
    const int ntile = blockIdx.x;
    const int ktile = blockIdx.y;
    const int tid = threadIdx.x;
    const int tr = tid >> 5, tc = tid & 31;
#pragma unroll
    for (int i = 0; i < 4; i++) {
        int kk = ktile * 32 + tr + i * 8;
        int n = ntile * 32 + tc;
        f[tr + i * 8][tc] = (n < VV) ? Wout[kk * VV + n] : 0.f;
    }
    __syncthreads();
#pragma unroll
    for (int i = 0; i < 4; i++) {
        int n = ntile * 32 + tr + i * 8;
        int kk = ktile * 32 + tc;
        float w = f[tc][tr + i * 8];
        __nv_bfloat16 bh = __float2bfloat16(w);
        __nv_bfloat16 bl = __float2bfloat16(w - __bfloat162float(bh));
        __nv_bfloat16* dst = g_B2 + (size_t)n * KEFF;
        dst[kk]        = bh;
        dst[512 + kk]  = bl;
        dst[1024 + kk] = bh;
    }
}

// ---------------- generic HMMA GEMM core (CTA 128x128, double-buffered) ----------------
template <int KEFFT, int KCMT, bool LOGITS>
__device__ __forceinline__ void hmma_gemm_body(
    const __nv_bfloat16* __restrict__ gA, const __nv_bfloat16* __restrict__ gB,
    const float* __restrict__ bias, float* __restrict__ out, int nt, int mt,
    __nv_bfloat16 (*sA)[128 * 40], __nv_bfloat16 (*sB)[128 * 40])
{
    const int tid = threadIdx.x;
    const int warp = tid >> 5, lane = tid & 31;
    const int wm = warp >> 2, wn = warp & 3;

    float acc[4][4][4];
#pragma unroll
    for (int a = 0; a < 4; a++)
#pragma unroll
        for (int b = 0; b < 4; b++)
#pragma unroll
            for (int c = 0; c < 4; c++) acc[a][b][c] = 0.f;

    uint4 pa[2], pb[2];
#pragma unroll
    for (int i = 0; i < 2; i++) {
        int s = tid + i * 256, r = s >> 2, sg = s & 3;
        pa[i] = *reinterpret_cast<const uint4*>(gA + (size_t)r * KEFFT + sg * 8);
        pb[i] = *reinterpret_cast<const uint4*>(gB + (size_t)r * KEFFT + sg * 8);
    }

    for (int kc = 0; kc < KCMT; kc++) {
        int buf = kc & 1;
#pragma unroll
        for (int i = 0; i < 2; i++) {
            int s = tid + i * 256, r = s >> 2, sg = s & 3;
            *reinterpret_cast<uint4*>(&sA[buf][r * 40 + sg * 8]) = pa[i];
            *reinterpret_cast<uint4*>(&sB[buf][r * 40 + sg * 8]) = pb[i];
        }
        __syncthreads();

        if (kc + 1 < KCMT) {
            int k0 = (kc + 1) * 32;
#pragma unroll
            for (int i = 0; i < 2; i++) {
                int s = tid + i * 256, r = s >> 2, sg = s & 3;
                pa[i] = *reinterpret_cast<const uint4*>(gA + (size_t)r * KEFFT + k0 + sg * 8);
                pb[i] = *reinterpret_cast<const uint4*>(gB + (size_t)r * KEFFT + k0 + sg * 8);
            }
        }

        unsigned sAb = smem_u32(sA[buf]);
        unsigned sBb = smem_u32(sB[buf]);
#pragma unroll
        for (int kf = 0; kf < 2; kf++) {
            unsigned a[4][4], b[4][2];
#pragma unroll
            for (int mf = 0; mf < 4; mf++) {
                int r = wm * 64 + mf * 16 + (lane & 15);
                ldmx4(a[mf], sAb + r * 80 + kf * 32 + (lane >> 4) * 16);
            }
#pragma unroll
            for (int nf = 0; nf < 4; nf++) {
                int n = wn * 32 + nf * 8 + (lane & 7);
                ldmx2(b[nf], sBb + n * 80 + kf * 32 + ((lane >> 3) & 1) * 16);
            }
#pragma unroll
            for (int mf = 0; mf < 4; mf++)
#pragma unroll
                for (int nf = 0; nf < 4; nf++)
                    mma16816(acc[mf][nf], a[mf], b[nf]);
        }
        __syncthreads();
    }

    const int gID = lane >> 2, tig = lane & 3;
#pragma unroll
    for (int mf = 0; mf < 4; mf++) {
#pragma unroll
        for (int half = 0; half < 2; half++) {
            int gm = mt * 128 + wm * 64 + mf * 16 + gID + half * 8;
            float* orow;
            if (LOGITS) {
                int tt = gm >> 7, bb = gm & 127;
                orow = out + ((size_t)bb * TT + tt) * VV;
            } else {
                orow = out + (size_t)gm * 1536;
            }
#pragma unroll
            for (int nf = 0; nf < 4; nf++) {
                int n = nt * 128 + wn * 32 + nf * 8 + tig * 2;
                float v0 = acc[mf][nf][half * 2 + 0];
                float v1 = acc[mf][nf][half * 2 + 1];
                if (LOGITS) {
                    if (n + 1 < VV) {
                        float2 o = make_float2(v0 + bias[n], v1 + bias[n + 1]);
                        *reinterpret_cast<float2*>(orow + n) = o;
                    } else if (n < VV) {
                        orow[n] = v0 + bias[n];
                    }
                } else {
                    float2 o = make_float2(v0 + bias[n], v1 + bias[n + 1]);
                    *reinterpret_cast<float2*>(orow + n) = o;
                }
            }
        }
    }
}

__global__ void __launch_bounds__(256) k_logits_mma(const float* __restrict__ bout,
                                                    float* __restrict__ out)
{
    __shared__ __align__(16) __nv_bfloat16 sA[2][128 * 40];
    __shared__ __align__(16) __nv_bfloat16 sB[2][128 * 40];
    const int nt = blockIdx.x, mt = blockIdx.y;
    hmma_gemm_body<KEFF, KCM, true>(
        g_A2 + (size_t)(mt * 128) * KEFF, g_B2 + (size_t)(nt * 128) * KEFF,
        bout, out, nt, mt, sA, sB);
}

__global__ void __launch_bounds__(256) k_precompute_mma(float* __restrict__ dummy)
{
    __shared__ __align__(16) __nv_bfloat16 sA[2][128 * 40];
    __shared__ __align__(16) __nv_bfloat16 sB[2][128 * 40];
    const int nt = blockIdx.x, mt = blockIdx.y;
    hmma_gemm_body<KEFF2, KCM2, false>(
        g_A2x + (size_t)(mt * 128) * KEFF2, g_B2x + (size_t)(nt * 128) * KEFF2,
        g_bx0, g_X0, nt, mt, sA, sB);
}

__global__ void k_hidden(float* __restrict__ outh) {
    int i = blockIdx.x * blockDim.x + threadIdx.x;
    if (i < BB * HH) {
        outh[i]           = g_h0[1][i];
        outh[BB * HH + i] = g_h1[1][i];
    }
}

// ---------------- launch ----------------
extern "C" void kernel_launch(void* const* d_in, const int* in_sizes, int n_in,
                              void* d_out, int out_size) {
    const int*   tokens = (const int*)d_in[0];     // int32 (JAX x64 disabled)
    const float* cnn  = (const float*)d_in[1];
    const float* emb  = (const float*)d_in[2];
    const float* Win  = (const float*)d_in[3];
    const float* bin  = (const float*)d_in[4];
    const float* Wout = (const float*)d_in[5];
    const float* bout = (const float*)d_in[6];
    const float* Wu0  = (const float*)d_in[7];
    const float* bu0  = (const float*)d_in[8];
    const float* Wr0  = (const float*)d_in[9];
    const float* br0  = (const float*)d_in[10];
    const float* Wc0  = (const float*)d_in[11];
    const float* bc0  = (const float*)d_in[12];
    const float* Wu1  = (const float*)d_in[13];
    const float* bu1  = (const float*)d_in[14];
    const float* Wr1  = (const float*)d_in[15];
    const float* br1  = (const float*)d_in[16];
    const float* Wc1  = (const float*)d_in[17];
    const float* bc1  = (const float*)d_in[18];
    float* out = (float*)d_out;

    cudaFuncSetAttribute(k_recurrence, cudaFuncAttributeMaxDynamicSharedMemorySize, RC_SMEM);

    k_pack<<<8, 256>>>(bu1, br1, bu0, br0, bc0);

    // one-time weight splits
    k_cvtW<<<dim3(32, 32, 4), 256>>>(Wu0, Wr0, Wc0, Wu1, Wr1, Wc1);
    k_cvtBx<<<dim3(48, 32), 256>>>(Wu0, Wr0, Wc0);
    k_cvtB<<<dim3(NPAD / 32, 512 / 32), 256>>>(Wout);

    // input layer: p = leaky_relu(cnn @ Win + bin)
    small_gemm<NFE, OpP><<<dim3(MAPS / 32, BB / 32), 256>>>(OpP{cnn, Win, bin});

    // precompute X0 via HMMA
    k_cvtAx<<<TT * BB, 256>>>(tokens, emb);
    k_precompute_mma<<<dim3(1536 / 128, (TT * BB) / 128), 256>>>(nullptr);

    // 25-step recurrence (HMMA persistent, weights resident in smem)
    k_recurrence<<<NBLK, 512, RC_SMEM>>>(bc1);

    // HMMA logits
    k_logits_mma<<<dim3(NPAD / 128, (TT * BB) / 128), 256>>>(bout, out);

    k_hidden<<<(BB * HH + 255) / 256, 256>>>(out + (size_t)BB * TT * VV);
}